// round 7
// baseline (speedup 1.0000x reference)
#include <cuda_runtime.h>
#include <cuda_bf16.h>
#include <math.h>

#define NN 50000
#define DIN 128
#define HH 256
#define DOUT 256

typedef unsigned long long ULL;

// ---- scratch (device globals; no allocation allowed) ----
__device__ float g_h[NN * HH];     // current activations
__device__ float g_hW[NN * HH];    // h @ W scratch
__device__ float g_agg[NN * HH];   // aggregation scratch / logits
__device__ float g_deg[NN];
__device__ float g_dinv[NN];

// packed fp32x2 FMA (Blackwell): d = a*b + c elementwise on 2 floats
__device__ __forceinline__ ULL ffma2(ULL a, ULL b, ULL c) {
    ULL d;
    asm("fma.rn.f32x2 %0, %1, %2, %3;" : "=l"(d) : "l"(a), "l"(b), "l"(c));
    return d;
}
__device__ __forceinline__ ULL dup2(float x) {
    ULL r;
    asm("mov.b64 %0, {%1, %1};" : "=l"(r) : "f"(x));
    return r;
}
__device__ __forceinline__ float lo32(ULL v) { return __uint_as_float((unsigned)(v & 0xffffffffull)); }
__device__ __forceinline__ float hi32(ULL v) { return __uint_as_float((unsigned)(v >> 32)); }

// ============================================================
// SGEMM with packed f32x2 FMA.
// C[M,Nc] = A[M,K] @ B[K,Nc] (+bias)(relu); SELF also writes C2 = C*dinv[row]^2
// BM=256 BN=128 BK=16, 256 threads, per-thread 16 rows x 8 cols.
// Row-pairs packed in f32x2 (natural from transposed A tile);
// B tile stored DUPLICATED in shared as f32x2 so b-operand is one LDS.64.
// ============================================================
template <bool BIAS, bool RELU, bool SELF>
__global__ __launch_bounds__(256, 1) void sgemm2_kernel(
    const float* __restrict__ A, const float* __restrict__ B,
    const float* __restrict__ bias, float* __restrict__ C,
    float* __restrict__ C2, int M, int K, int Nc)
{
    const int BM = 256, BN = 128, BK = 16;
    __shared__ float As[BK][BM + 4];          // transposed A tile
    __shared__ ULL   Bsd[BK][BN];             // duplicated B tile

    int tid = threadIdx.x;
    int tx = tid & 15;            // col group: owns cols tx + 16*c, c=0..7
    int ty = tid >> 4;            // row group: owns rows ty*16 .. ty*16+15
    int rowBase = blockIdx.x * BM;
    int colBase = blockIdx.y * BN;

    ULL acc[8][8];                // [row-pair p][col c]
#pragma unroll
    for (int p = 0; p < 8; p++)
#pragma unroll
        for (int c = 0; c < 8; c++) acc[p][c] = 0ull;

    int nK = K / BK;
    for (int t = 0; t < nK; t++) {
        int kBase = t * BK;
        // ---- load A tile (BM x BK) transposed into As[BK][BM] ----
#pragma unroll
        for (int it = 0; it < 4; it++) {
            int idx = tid + it * 256;        // 0..1023 float4 slots
            int r = idx >> 2;                // 0..255
            int c4 = idx & 3;                // 0..3
            int grow = rowBase + r;
            float4 v = make_float4(0.f, 0.f, 0.f, 0.f);
            if (grow < M)
                v = *(const float4*)&A[(size_t)grow * K + kBase + c4 * 4];
            As[c4 * 4 + 0][r] = v.x;
            As[c4 * 4 + 1][r] = v.y;
            As[c4 * 4 + 2][r] = v.z;
            As[c4 * 4 + 3][r] = v.w;
        }
        // ---- load B tile (BK x BN), duplicated ----
        {
            int r  = tid >> 4;               // 0..15
            int cc = tid & 15;               // 0..15 -> 8 cols each
            const float* bp = &B[(size_t)(kBase + r) * Nc + colBase + cc * 8];
            float4 v0 = *(const float4*)&bp[0];
            float4 v1 = *(const float4*)&bp[4];
            ULL* bd = &Bsd[r][cc * 8];
            bd[0] = dup2(v0.x); bd[1] = dup2(v0.y);
            bd[2] = dup2(v0.z); bd[3] = dup2(v0.w);
            bd[4] = dup2(v1.x); bd[5] = dup2(v1.y);
            bd[6] = dup2(v1.z); bd[7] = dup2(v1.w);
        }
        __syncthreads();

#pragma unroll
        for (int kk = 0; kk < BK; kk++) {
            // a: 8 row-pairs (natural packing, 16B-aligned)
            ulonglong2 a01 = *(const ulonglong2*)&As[kk][ty * 16 + 0];
            ulonglong2 a23 = *(const ulonglong2*)&As[kk][ty * 16 + 4];
            ulonglong2 a45 = *(const ulonglong2*)&As[kk][ty * 16 + 8];
            ulonglong2 a67 = *(const ulonglong2*)&As[kk][ty * 16 + 12];
            ULL ap[8] = {a01.x, a01.y, a23.x, a23.y, a45.x, a45.y, a67.x, a67.y};
            ULL bd[8];
#pragma unroll
            for (int c = 0; c < 8; c++) bd[c] = Bsd[kk][tx + 16 * c];
#pragma unroll
            for (int p = 0; p < 8; p++)
#pragma unroll
                for (int c = 0; c < 8; c++)
                    acc[p][c] = ffma2(ap[p], bd[c], acc[p][c]);
        }
        __syncthreads();
    }

    // ---- epilogue ----
    float bia[8];
    if (BIAS) {
#pragma unroll
        for (int c = 0; c < 8; c++) bia[c] = bias[colBase + tx + 16 * c];
    }
#pragma unroll
    for (int p = 0; p < 8; p++) {
#pragma unroll
        for (int hh = 0; hh < 2; hh++) {
            int grow = rowBase + ty * 16 + 2 * p + hh;
            if (grow >= M) continue;
            float s = 0.f;
            if (SELF) { float dv = g_dinv[grow]; s = dv * dv; }
            float* cp  = &C[(size_t)grow * Nc + colBase];
            float* cp2 = SELF ? &C2[(size_t)grow * Nc + colBase] : nullptr;
#pragma unroll
            for (int c = 0; c < 8; c++) {
                float v = hh ? hi32(acc[p][c]) : lo32(acc[p][c]);
                if (BIAS) v += bia[c];
                if (RELU) v = fmaxf(v, 0.0f);
                cp[tx + 16 * c] = v;
                if (SELF) cp2[tx + 16 * c] = v * s;
            }
        }
    }
}

// ============================================================
// graph helpers  (edge_index is INT32: src = ei[e], dst = ei[E+e])
// ============================================================
__global__ void zero_deg_kernel() {
    int i = blockIdx.x * blockDim.x + threadIdx.x;
    if (i < NN) g_deg[i] = 0.0f;
}

__global__ void deg_count_kernel(const int* __restrict__ ei, int E) {
    int e = blockIdx.x * blockDim.x + threadIdx.x;
    if (e < E) {
        int d = ei[E + e];
        if ((unsigned)d < (unsigned)NN) atomicAdd(&g_deg[d], 1.0f);
    }
}

__global__ void dinv_kernel() {
    int i = blockIdx.x * blockDim.x + threadIdx.x;
    if (i < NN) g_dinv[i] = rsqrtf(g_deg[i] + 1.0f);
}

// one warp per edge: agg[dst] += hW[src] * dinv[src]*dinv[dst]
__global__ void scatter_kernel(const float* __restrict__ hW,
                               const int* __restrict__ ei,
                               float* __restrict__ agg, int E)
{
    int warp = (blockIdx.x * blockDim.x + threadIdx.x) >> 5;
    int lane = threadIdx.x & 31;
    if (warp >= E) return;
    int s = ei[warp];
    int d = ei[E + warp];
    if ((unsigned)s >= (unsigned)NN || (unsigned)d >= (unsigned)NN) return;
    float norm = g_dinv[s] * g_dinv[d];
    const float4* sp = (const float4*)(hW + (size_t)s * HH);
    float* dp = agg + (size_t)d * HH;
#pragma unroll
    for (int it = 0; it < 2; it++) {
        int i = lane + it * 32;           // 0..63 float4s
        float4 v = sp[i];
        atomicAdd(&dp[i * 4 + 0], v.x * norm);
        atomicAdd(&dp[i * 4 + 1], v.y * norm);
        atomicAdd(&dp[i * 4 + 2], v.z * norm);
        atomicAdd(&dp[i * 4 + 3], v.w * norm);
    }
}

// h = relu(agg + bias)
__global__ void bias_relu_kernel(const float* __restrict__ agg,
                                 const float* __restrict__ bias,
                                 float* __restrict__ h)
{
    int i = blockIdx.x * blockDim.x + threadIdx.x;
    if (i >= NN * (HH / 4)) return;
    int c4 = i & 63;
    float4 b = ((const float4*)bias)[c4];
    float4 v = ((const float4*)agg)[i];
    v.x = fmaxf(v.x + b.x, 0.0f);
    v.y = fmaxf(v.y + b.y, 0.0f);
    v.z = fmaxf(v.z + b.z, 0.0f);
    v.w = fmaxf(v.w + b.w, 0.0f);
    ((float4*)h)[i] = v;
}

// softmax per row, one warp per row (256 cols = 2 float4/lane)
__global__ void softmax_kernel(const float* __restrict__ in, float* __restrict__ out) {
    int warp = (blockIdx.x * blockDim.x + threadIdx.x) >> 5;
    int lane = threadIdx.x & 31;
    if (warp >= NN) return;
    const float4* ip = (const float4*)(in + (size_t)warp * DOUT);
    float4 a = ip[lane];
    float4 b = ip[lane + 32];
    float m = fmaxf(fmaxf(fmaxf(a.x, a.y), fmaxf(a.z, a.w)),
                    fmaxf(fmaxf(b.x, b.y), fmaxf(b.z, b.w)));
#pragma unroll
    for (int o = 16; o > 0; o >>= 1)
        m = fmaxf(m, __shfl_xor_sync(0xFFFFFFFFu, m, o));
    a.x = __expf(a.x - m); a.y = __expf(a.y - m); a.z = __expf(a.z - m); a.w = __expf(a.w - m);
    b.x = __expf(b.x - m); b.y = __expf(b.y - m); b.z = __expf(b.z - m); b.w = __expf(b.w - m);
    float s = a.x + a.y + a.z + a.w + b.x + b.y + b.z + b.w;
#pragma unroll
    for (int o = 16; o > 0; o >>= 1)
        s += __shfl_xor_sync(0xFFFFFFFFu, s, o);
    float inv = 1.0f / s;
    a.x *= inv; a.y *= inv; a.z *= inv; a.w *= inv;
    b.x *= inv; b.y *= inv; b.z *= inv; b.w *= inv;
    float4* op = (float4*)(out + (size_t)warp * DOUT);
    op[lane] = a;
    op[lane + 32] = b;
}

// ============================================================
// host launch
// ============================================================
extern "C" void kernel_launch(void* const* d_in, const int* in_sizes, int n_in,
                              void* d_out, int out_size)
{
    const float* x    = (const float*)d_in[0];
    const int* ei     = (const int*)d_in[1];   // int32
    const float* W1  = (const float*)d_in[2];
    const float* b1  = (const float*)d_in[3];
    const float* Wg1 = (const float*)d_in[4];
    const float* bg1 = (const float*)d_in[5];
    const float* Wg2 = (const float*)d_in[6];
    const float* bg2 = (const float*)d_in[7];
    const float* W2  = (const float*)d_in[8];
    const float* b2  = (const float*)d_in[9];
    const float* W3  = (const float*)d_in[10];
    const float* b3  = (const float*)d_in[11];
    float* out = (float*)d_out;

    int E = in_sizes[1] / 2;

    float *h, *hW, *agg;
    cudaGetSymbolAddress((void**)&h, g_h);
    cudaGetSymbolAddress((void**)&hW, g_hW);
    cudaGetSymbolAddress((void**)&agg, g_agg);

    const int ELEM4 = NN * (HH / 4);
    dim3 gemmGrid((NN + 255) / 256, HH / 128);

    // layer 1: h = relu(x @ W1 + b1), K=128
    sgemm2_kernel<true, true, false><<<gemmGrid, 256>>>(x, W1, b1, h, nullptr, NN, DIN, HH);

    // degrees (shared by both convs)
    zero_deg_kernel<<<(NN + 255) / 256, 256>>>();
    deg_count_kernel<<<(E + 255) / 256, 256>>>(ei, E);
    dinv_kernel<<<(NN + 255) / 256, 256>>>();

    // conv 1: hW = h@Wg1, agg = hW*dinv^2 fused in epilogue
    sgemm2_kernel<false, false, true><<<gemmGrid, 256>>>(h, Wg1, nullptr, hW, agg, NN, HH, HH);
    scatter_kernel<<<(E * 32 + 255) / 256, 256>>>(hW, ei, agg, E);
    bias_relu_kernel<<<(ELEM4 + 255) / 256, 256>>>(agg, bg1, h);

    // conv 2
    sgemm2_kernel<false, false, true><<<gemmGrid, 256>>>(h, Wg2, nullptr, hW, agg, NN, HH, HH);
    scatter_kernel<<<(E * 32 + 255) / 256, 256>>>(hW, ei, agg, E);
    bias_relu_kernel<<<(ELEM4 + 255) / 256, 256>>>(agg, bg2, h);

    // layer 4: hW = relu(h @ W2 + b2)
    sgemm2_kernel<true, true, false><<<gemmGrid, 256>>>(h, W2, b2, hW, nullptr, NN, HH, HH);

    // layer 5 logits: agg = hW @ W3 + b3
    sgemm2_kernel<true, false, false><<<gemmGrid, 256>>>(hW, W3, b3, agg, nullptr, NN, HH, DOUT);

    // softmax -> out
    softmax_kernel<<<(NN * 32 + 255) / 256, 256>>>(agg, out);
}

// round 9
// speedup vs baseline: 1.3452x; 1.3452x over previous
#include <cuda_runtime.h>
#include <cuda_bf16.h>
#include <math.h>

#define NN 50000
#define DIN 128
#define HH 256
#define DOUT 256

// ---- scratch (device globals; no allocation allowed) ----
__device__ float g_h[NN * HH];
__device__ float g_hW[NN * HH];
__device__ float g_agg[NN * HH];
__device__ float g_deg[NN];
__device__ float g_dinv[NN];

// packed weights: per weight, per term: [nh 2][chunk K/32][kp 16][n 128] bf16x2 (swizzled)
#define WPACK 131072  // bytes per weight per term (max K=256)
__device__ __align__(16) unsigned char g_packh[5 * WPACK];
__device__ __align__(16) unsigned char g_packl[5 * WPACK];

// ============================================================
// mma.sync m16n8k16 bf16 (row.col), fp32 accum
// ============================================================
__device__ __forceinline__ void mma16816(float* c, const unsigned* a, const unsigned* b) {
    asm volatile(
        "mma.sync.aligned.m16n8k16.row.col.f32.bf16.bf16.f32 "
        "{%0,%1,%2,%3}, {%4,%5,%6,%7}, {%8,%9}, {%0,%1,%2,%3};"
        : "+f"(c[0]), "+f"(c[1]), "+f"(c[2]), "+f"(c[3])
        : "r"(a[0]), "r"(a[1]), "r"(a[2]), "r"(a[3]), "r"(b[0]), "r"(b[1]));
}

__device__ __forceinline__ unsigned pack_bf2(__nv_bfloat16 x, __nv_bfloat16 y) {
    return ((unsigned)__bfloat16_as_ushort(y) << 16) | __bfloat16_as_ushort(x);
}

// ============================================================
// weight prepack: W[K,256] fp32 -> hi/lo bf16x2 fragment layout
// ============================================================
__global__ void pack_weights_kernel(const float* W1, const float* Wg1, const float* Wg2,
                                    const float* W2, const float* W3) {
    int wi = blockIdx.y;
    const float* W = (wi == 0) ? W1 : (wi == 1) ? Wg1 : (wi == 2) ? Wg2 : (wi == 3) ? W2 : W3;
    int K = (wi == 0) ? DIN : HH;
    int i = blockIdx.x * blockDim.x + threadIdx.x;
    if (i >= K * 256) return;
    int k = i >> 8, n = i & 255;
    float w = W[i];
    __nv_bfloat16 h = __float2bfloat16(w);
    __nv_bfloat16 l = __float2bfloat16(w - __bfloat162float(h));
    int c = k >> 5, kl = k & 31;
    int kp = kl >> 1, hl = kl & 1;
    int nh = n >> 7, nl = n & 127;
    int col = nl ^ ((kp & 3) << 3);
    size_t off = (size_t)wi * WPACK + ((size_t)(nh * (K >> 5) + c)) * 8192
               + kp * 512 + col * 4 + hl * 2;
    *(__nv_bfloat16*)(g_packh + off) = h;
    *(__nv_bfloat16*)(g_packl + off) = l;
}

// ============================================================
// HMMA GEMM: C[M,256] = A[M,K] @ W (+bias)(relu); SELF: C2 = C*dinv[row]^2
// CTA 128 rows x 128 cols (grid.y = col half), 8 warps (2M x 4N), warp m64n32.
// BK=32. bf16 2-term split: Ah*Bh + Ah*Bl + Al*Bh, fp32 accum.
// ============================================================
template <bool BIAS, bool RELU, bool SELF>
__global__ __launch_bounds__(256, 1) void hmma_gemm_kernel(
    const float* __restrict__ A, const unsigned char* __restrict__ Bhp,
    const unsigned char* __restrict__ Blp, const float* __restrict__ bias,
    float* __restrict__ C, float* __restrict__ C2, int M, int K)
{
    __shared__ __align__(16) unsigned Ahs[16 * 128];
    __shared__ __align__(16) unsigned Als[16 * 128];
    __shared__ __align__(16) unsigned Bhs[16 * 128];
    __shared__ __align__(16) unsigned Bls[16 * 128];

    int tid = threadIdx.x;
    int lane = tid & 31;
    int wid = tid >> 5;
    int wm = wid & 1;        // 0..1 -> 64 rows each
    int wn = wid >> 1;       // 0..3 -> 32 cols each
    int row0 = blockIdx.x * 128;
    int colBlock = blockIdx.y * 128;
    int chunks = K >> 5;

    const unsigned* Bhg = (const unsigned*)Bhp + (size_t)blockIdx.y * chunks * 2048;
    const unsigned* Blg = (const unsigned*)Blp + (size_t)blockIdx.y * chunks * 2048;

    float acc[4][4][4];
#pragma unroll
    for (int mt = 0; mt < 4; mt++)
#pragma unroll
        for (int nt = 0; nt < 4; nt++)
#pragma unroll
            for (int q = 0; q < 4; q++) acc[mt][nt][q] = 0.0f;

    for (int c = 0; c < chunks; c++) {
        // ---- stage A: 128 rows x 16 k-pairs, fp32 -> hi/lo bf16x2, swizzled ----
#pragma unroll
        for (int it = 0; it < 8; it++) {
            int slot = tid + it * 256;     // 0..2047
            int kp = slot & 15;
            int r = slot >> 4;
            int grow = row0 + r;
            float2 v = make_float2(0.f, 0.f);
            if (grow < M)
                v = *(const float2*)&A[(size_t)grow * K + c * 32 + kp * 2];
            __nv_bfloat16 h0 = __float2bfloat16(v.x), h1 = __float2bfloat16(v.y);
            __nv_bfloat16 l0 = __float2bfloat16(v.x - __bfloat162float(h0));
            __nv_bfloat16 l1 = __float2bfloat16(v.y - __bfloat162float(h1));
            int dst = kp * 128 + (r ^ ((kp & 3) << 3));
            Ahs[dst] = pack_bf2(h0, h1);
            Als[dst] = pack_bf2(l0, l1);
        }
        // ---- stage B: linear copy of pre-swizzled 8KB blocks ----
        {
            const uint4* sh = (const uint4*)(Bhg + c * 2048);
            const uint4* sl = (const uint4*)(Blg + c * 2048);
            uint4* dh = (uint4*)Bhs;
            uint4* dl = (uint4*)Bls;
#pragma unroll
            for (int it = 0; it < 2; it++) {
                int i = tid + it * 256;    // 0..511 uint4
                dh[i] = sh[i];
                dl[i] = sl[i];
            }
        }
        __syncthreads();

#pragma unroll
        for (int j = 0; j < 2; j++) {       // two k16 steps per chunk
            unsigned bfh[4][2], bfl[4][2];
#pragma unroll
            for (int nt = 0; nt < 4; nt++) {
                int n = wn * 32 + nt * 8 + (lane >> 2);
#pragma unroll
                for (int q = 0; q < 2; q++) {
                    int kp = j * 8 + q * 4 + (lane & 3);
                    int idx = kp * 128 + (n ^ ((kp & 3) << 3));
                    bfh[nt][q] = Bhs[idx];
                    bfl[nt][q] = Bls[idx];
                }
            }
            unsigned afh[4][4], afl[4][4];
#pragma unroll
            for (int mt = 0; mt < 4; mt++) {
                int rbase = wm * 64 + mt * 16 + (lane >> 2);
#pragma unroll
                for (int q = 0; q < 4; q++) {
                    int r = rbase + ((q & 1) ? 8 : 0);
                    int kp = j * 8 + ((q & 2) ? 4 : 0) + (lane & 3);
                    int idx = kp * 128 + (r ^ ((kp & 3) << 3));
                    afh[mt][q] = Ahs[idx];
                    afl[mt][q] = Als[idx];
                }
            }
#pragma unroll
            for (int mt = 0; mt < 4; mt++)
#pragma unroll
                for (int nt = 0; nt < 4; nt++) {
                    mma16816(acc[mt][nt], afh[mt], bfh[nt]);
                    mma16816(acc[mt][nt], afh[mt], bfl[nt]);
                    mma16816(acc[mt][nt], afl[mt], bfh[nt]);
                }
        }
        __syncthreads();
    }

    // ---- epilogue ----
#pragma unroll
    for (int mt = 0; mt < 4; mt++) {
        int r0 = row0 + wm * 64 + mt * 16 + (lane >> 2);
#pragma unroll
        for (int nt = 0; nt < 4; nt++) {
            int col = colBlock + wn * 32 + nt * 8 + (lane & 3) * 2;
            float b0 = 0.f, b1 = 0.f;
            if (BIAS) { b0 = bias[col]; b1 = bias[col + 1]; }
#pragma unroll
            for (int hh = 0; hh < 2; hh++) {
                int r = r0 + hh * 8;
                if (r >= M) continue;
                float v0 = acc[mt][nt][hh * 2 + 0];
                float v1 = acc[mt][nt][hh * 2 + 1];
                if (BIAS) { v0 += b0; v1 += b1; }
                if (RELU) { v0 = fmaxf(v0, 0.f); v1 = fmaxf(v1, 0.f); }
                *(float2*)&C[(size_t)r * 256 + col] = make_float2(v0, v1);
                if (SELF) {
                    float dv = g_dinv[r];
                    float s = dv * dv;
                    *(float2*)&C2[(size_t)r * 256 + col] = make_float2(v0 * s, v1 * s);
                }
            }
        }
    }
}

// ============================================================
// graph helpers (edge_index is INT32: src = ei[e], dst = ei[E+e])
// ============================================================
__global__ void zero_deg_kernel() {
    int i = blockIdx.x * blockDim.x + threadIdx.x;
    if (i < NN) g_deg[i] = 0.0f;
}
__global__ void deg_count_kernel(const int* __restrict__ ei, int E) {
    int e = blockIdx.x * blockDim.x + threadIdx.x;
    if (e < E) {
        int d = ei[E + e];
        if ((unsigned)d < (unsigned)NN) atomicAdd(&g_deg[d], 1.0f);
    }
}
__global__ void dinv_kernel() {
    int i = blockIdx.x * blockDim.x + threadIdx.x;
    if (i < NN) g_dinv[i] = rsqrtf(g_deg[i] + 1.0f);
}

__global__ void scatter_kernel(const float* __restrict__ hW,
                               const int* __restrict__ ei,
                               float* __restrict__ agg, int E)
{
    int warp = (blockIdx.x * blockDim.x + threadIdx.x) >> 5;
    int lane = threadIdx.x & 31;
    if (warp >= E) return;
    int s = ei[warp];
    int d = ei[E + warp];
    if ((unsigned)s >= (unsigned)NN || (unsigned)d >= (unsigned)NN) return;
    float norm = g_dinv[s] * g_dinv[d];
    const float4* sp = (const float4*)(hW + (size_t)s * HH);
    float* dp = agg + (size_t)d * HH;
#pragma unroll
    for (int it = 0; it < 2; it++) {
        int i = lane + it * 32;
        float4 v = sp[i];
        atomicAdd(&dp[i * 4 + 0], v.x * norm);
        atomicAdd(&dp[i * 4 + 1], v.y * norm);
        atomicAdd(&dp[i * 4 + 2], v.z * norm);
        atomicAdd(&dp[i * 4 + 3], v.w * norm);
    }
}

__global__ void bias_relu_kernel(const float* __restrict__ agg,
                                 const float* __restrict__ bias,
                                 float* __restrict__ h)
{
    int i = blockIdx.x * blockDim.x + threadIdx.x;
    if (i >= NN * (HH / 4)) return;
    int c4 = i & 63;
    float4 b = ((const float4*)bias)[c4];
    float4 v = ((const float4*)agg)[i];
    v.x = fmaxf(v.x + b.x, 0.0f);
    v.y = fmaxf(v.y + b.y, 0.0f);
    v.z = fmaxf(v.z + b.z, 0.0f);
    v.w = fmaxf(v.w + b.w, 0.0f);
    ((float4*)h)[i] = v;
}

__global__ void softmax_kernel(const float* __restrict__ in, float* __restrict__ out) {
    int warp = (blockIdx.x * blockDim.x + threadIdx.x) >> 5;
    int lane = threadIdx.x & 31;
    if (warp >= NN) return;
    const float4* ip = (const float4*)(in + (size_t)warp * DOUT);
    float4 a = ip[lane];
    float4 b = ip[lane + 32];
    float m = fmaxf(fmaxf(fmaxf(a.x, a.y), fmaxf(a.z, a.w)),
                    fmaxf(fmaxf(b.x, b.y), fmaxf(b.z, b.w)));
#pragma unroll
    for (int o = 16; o > 0; o >>= 1)
        m = fmaxf(m, __shfl_xor_sync(0xFFFFFFFFu, m, o));
    a.x = __expf(a.x - m); a.y = __expf(a.y - m); a.z = __expf(a.z - m); a.w = __expf(a.w - m);
    b.x = __expf(b.x - m); b.y = __expf(b.y - m); b.z = __expf(b.z - m); b.w = __expf(b.w - m);
    float s = a.x + a.y + a.z + a.w + b.x + b.y + b.z + b.w;
#pragma unroll
    for (int o = 16; o > 0; o >>= 1)
        s += __shfl_xor_sync(0xFFFFFFFFu, s, o);
    float inv = 1.0f / s;
    a.x *= inv; a.y *= inv; a.z *= inv; a.w *= inv;
    b.x *= inv; b.y *= inv; b.z *= inv; b.w *= inv;
    float4* op = (float4*)(out + (size_t)warp * DOUT);
    op[lane] = a;
    op[lane + 32] = b;
}

// ============================================================
// host launch
// ============================================================
extern "C" void kernel_launch(void* const* d_in, const int* in_sizes, int n_in,
                              void* d_out, int out_size)
{
    const float* x    = (const float*)d_in[0];
    const int* ei     = (const int*)d_in[1];   // int32
    const float* W1  = (const float*)d_in[2];
    const float* b1  = (const float*)d_in[3];
    const float* Wg1 = (const float*)d_in[4];
    const float* bg1 = (const float*)d_in[5];
    const float* Wg2 = (const float*)d_in[6];
    const float* bg2 = (const float*)d_in[7];
    const float* W2  = (const float*)d_in[8];
    const float* b2  = (const float*)d_in[9];
    const float* W3  = (const float*)d_in[10];
    const float* b3  = (const float*)d_in[11];
    float* out = (float*)d_out;

    int E = in_sizes[1] / 2;

    float *h, *hW, *agg;
    unsigned char *ph, *pl;
    cudaGetSymbolAddress((void**)&h, g_h);
    cudaGetSymbolAddress((void**)&hW, g_hW);
    cudaGetSymbolAddress((void**)&agg, g_agg);
    cudaGetSymbolAddress((void**)&ph, g_packh);
    cudaGetSymbolAddress((void**)&pl, g_packl);

    const int ELEM4 = NN * (HH / 4);
    dim3 gemmGrid((NN + 127) / 128, 2);

    // 1: pack all weights
    {
        dim3 pg((256 * 256 + 255) / 256, 5);
        pack_weights_kernel<<<pg, 256>>>(W1, Wg1, Wg2, W2, W3);
    }
    // 2-4: degrees
    zero_deg_kernel<<<(NN + 255) / 256, 256>>>();
    deg_count_kernel<<<(E + 255) / 256, 256>>>(ei, E);
    dinv_kernel<<<(NN + 255) / 256, 256>>>();

    // 5: layer 1 — h = relu(x @ W1 + b1), K=128
    hmma_gemm_kernel<true, true, false><<<gemmGrid, 256>>>(
        x, ph + 0 * WPACK, pl + 0 * WPACK, b1, h, nullptr, NN, DIN);

    // conv 1: hW = h@Wg1, agg = hW*dinv^2 fused
    hmma_gemm_kernel<false, false, true><<<gemmGrid, 256>>>(
        h, ph + 1 * WPACK, pl + 1 * WPACK, nullptr, hW, agg, NN, HH);
    scatter_kernel<<<(E * 32 + 255) / 256, 256>>>(hW, ei, agg, E);
    bias_relu_kernel<<<(ELEM4 + 255) / 256, 256>>>(agg, bg1, h);

    // conv 2
    hmma_gemm_kernel<false, false, true><<<gemmGrid, 256>>>(
        h, ph + 2 * WPACK, pl + 2 * WPACK, nullptr, hW, agg, NN, HH);
    scatter_kernel<<<(E * 32 + 255) / 256, 256>>>(hW, ei, agg, E);
    bias_relu_kernel<<<(ELEM4 + 255) / 256, 256>>>(agg, bg2, h);

    // layer 4: hW = relu(h @ W2 + b2)
    hmma_gemm_kernel<true, true, false><<<gemmGrid, 256>>>(
        h, ph + 3 * WPACK, pl + 3 * WPACK, b2, hW, nullptr, NN, HH);

    // layer 5 logits: agg = hW @ W3 + b3
    hmma_gemm_kernel<true, false, false><<<gemmGrid, 256>>>(
        hW, ph + 4 * WPACK, pl + 4 * WPACK, b3, agg, nullptr, NN, HH);

    // softmax -> out
    softmax_kernel<<<(NN * 32 + 255) / 256, 256>>>(agg, out);
}

// round 10
// speedup vs baseline: 2.1325x; 1.5852x over previous
#include <cuda_runtime.h>
#include <cuda_bf16.h>
#include <math.h>

#define NN 50000
#define DIN 128
#define HH 256
#define DOUT 256
#define NBLK 196          // ceil(NN/256)
#define EMAXC 320000

// ---- scratch (device globals; no allocation allowed) ----
__device__ float g_h[NN * HH];
__device__ float g_hW[NN * HH];
__device__ float g_agg[NN * HH];
__device__ float g_dinv[NN];
__device__ int   g_degi[NN];
__device__ int   g_cursor[NN];
__device__ int   g_rowstart[NN];
__device__ int   g_esrc[EMAXC];
__device__ int   g_blocksum[256];

// packed weights: per weight, per term: [nh 2][chunk K/32][kp 16][n 128] bf16x2 (swizzled)
#define WPACK 131072
__device__ __align__(16) unsigned char g_packh[5 * WPACK];
__device__ __align__(16) unsigned char g_packl[5 * WPACK];

// ============================================================
// mma.sync m16n8k16 bf16 (row.col), fp32 accum
// ============================================================
__device__ __forceinline__ void mma16816(float* c, const unsigned* a, const unsigned* b) {
    asm volatile(
        "mma.sync.aligned.m16n8k16.row.col.f32.bf16.bf16.f32 "
        "{%0,%1,%2,%3}, {%4,%5,%6,%7}, {%8,%9}, {%0,%1,%2,%3};"
        : "+f"(c[0]), "+f"(c[1]), "+f"(c[2]), "+f"(c[3])
        : "r"(a[0]), "r"(a[1]), "r"(a[2]), "r"(a[3]), "r"(b[0]), "r"(b[1]));
}

__device__ __forceinline__ unsigned pack_bf2(__nv_bfloat16 x, __nv_bfloat16 y) {
    return ((unsigned)__bfloat16_as_ushort(y) << 16) | __bfloat16_as_ushort(x);
}

// ============================================================
// weight prepack: W[K,256] fp32 -> hi/lo bf16x2 fragment layout
// ============================================================
__global__ void pack_weights_kernel(const float* W1, const float* Wg1, const float* Wg2,
                                    const float* W2, const float* W3) {
    int wi = blockIdx.y;
    const float* W = (wi == 0) ? W1 : (wi == 1) ? Wg1 : (wi == 2) ? Wg2 : (wi == 3) ? W2 : W3;
    int K = (wi == 0) ? DIN : HH;
    int i = blockIdx.x * blockDim.x + threadIdx.x;
    if (i >= K * 256) return;
    int k = i >> 8, n = i & 255;
    float w = W[i];
    __nv_bfloat16 h = __float2bfloat16(w);
    __nv_bfloat16 l = __float2bfloat16(w - __bfloat162float(h));
    int c = k >> 5, kl = k & 31;
    int kp = kl >> 1, hl = kl & 1;
    int nh = n >> 7, nl = n & 127;
    int col = nl ^ ((kp & 3) << 3);
    size_t off = (size_t)wi * WPACK + ((size_t)(nh * (K >> 5) + c)) * 8192
               + kp * 512 + col * 4 + hl * 2;
    *(__nv_bfloat16*)(g_packh + off) = h;
    *(__nv_bfloat16*)(g_packl + off) = l;
}

// ============================================================
// HMMA GEMM: C[M,256] = A[M,K] @ W (+bias)(relu)
// CTA 128 rows x 128 cols (grid.y = col half), 8 warps (2M x 4N), warp m64n32.
// ============================================================
template <bool BIAS, bool RELU>
__global__ __launch_bounds__(256, 1) void hmma_gemm_kernel(
    const float* __restrict__ A, const unsigned char* __restrict__ Bhp,
    const unsigned char* __restrict__ Blp, const float* __restrict__ bias,
    float* __restrict__ C, int M, int K)
{
    __shared__ __align__(16) unsigned Ahs[16 * 128];
    __shared__ __align__(16) unsigned Als[16 * 128];
    __shared__ __align__(16) unsigned Bhs[16 * 128];
    __shared__ __align__(16) unsigned Bls[16 * 128];

    int tid = threadIdx.x;
    int lane = tid & 31;
    int wid = tid >> 5;
    int wm = wid & 1;
    int wn = wid >> 1;
    int row0 = blockIdx.x * 128;
    int colBlock = blockIdx.y * 128;
    int chunks = K >> 5;

    const unsigned* Bhg = (const unsigned*)Bhp + (size_t)blockIdx.y * chunks * 2048;
    const unsigned* Blg = (const unsigned*)Blp + (size_t)blockIdx.y * chunks * 2048;

    float acc[4][4][4];
#pragma unroll
    for (int mt = 0; mt < 4; mt++)
#pragma unroll
        for (int nt = 0; nt < 4; nt++)
#pragma unroll
            for (int q = 0; q < 4; q++) acc[mt][nt][q] = 0.0f;

    for (int c = 0; c < chunks; c++) {
#pragma unroll
        for (int it = 0; it < 8; it++) {
            int slot = tid + it * 256;
            int kp = slot & 15;
            int r = slot >> 4;
            int grow = row0 + r;
            float2 v = make_float2(0.f, 0.f);
            if (grow < M)
                v = *(const float2*)&A[(size_t)grow * K + c * 32 + kp * 2];
            __nv_bfloat16 h0 = __float2bfloat16(v.x), h1 = __float2bfloat16(v.y);
            __nv_bfloat16 l0 = __float2bfloat16(v.x - __bfloat162float(h0));
            __nv_bfloat16 l1 = __float2bfloat16(v.y - __bfloat162float(h1));
            int dst = kp * 128 + (r ^ ((kp & 3) << 3));
            Ahs[dst] = pack_bf2(h0, h1);
            Als[dst] = pack_bf2(l0, l1);
        }
        {
            const uint4* sh = (const uint4*)(Bhg + c * 2048);
            const uint4* sl = (const uint4*)(Blg + c * 2048);
            uint4* dh = (uint4*)Bhs;
            uint4* dl = (uint4*)Bls;
#pragma unroll
            for (int it = 0; it < 2; it++) {
                int i = tid + it * 256;
                dh[i] = sh[i];
                dl[i] = sl[i];
            }
        }
        __syncthreads();

#pragma unroll
        for (int j = 0; j < 2; j++) {
            unsigned bfh[4][2], bfl[4][2];
#pragma unroll
            for (int nt = 0; nt < 4; nt++) {
                int n = wn * 32 + nt * 8 + (lane >> 2);
#pragma unroll
                for (int q = 0; q < 2; q++) {
                    int kp = j * 8 + q * 4 + (lane & 3);
                    int idx = kp * 128 + (n ^ ((kp & 3) << 3));
                    bfh[nt][q] = Bhs[idx];
                    bfl[nt][q] = Bls[idx];
                }
            }
            unsigned afh[4][4], afl[4][4];
#pragma unroll
            for (int mt = 0; mt < 4; mt++) {
                int rbase = wm * 64 + mt * 16 + (lane >> 2);
#pragma unroll
                for (int q = 0; q < 4; q++) {
                    int r = rbase + ((q & 1) ? 8 : 0);
                    int kp = j * 8 + ((q & 2) ? 4 : 0) + (lane & 3);
                    int idx = kp * 128 + (r ^ ((kp & 3) << 3));
                    afh[mt][q] = Ahs[idx];
                    afl[mt][q] = Als[idx];
                }
            }
#pragma unroll
            for (int mt = 0; mt < 4; mt++)
#pragma unroll
                for (int nt = 0; nt < 4; nt++) {
                    mma16816(acc[mt][nt], afh[mt], bfh[nt]);
                    mma16816(acc[mt][nt], afh[mt], bfl[nt]);
                    mma16816(acc[mt][nt], afl[mt], bfh[nt]);
                }
        }
        __syncthreads();
    }

#pragma unroll
    for (int mt = 0; mt < 4; mt++) {
        int r0 = row0 + wm * 64 + mt * 16 + (lane >> 2);
#pragma unroll
        for (int nt = 0; nt < 4; nt++) {
            int col = colBlock + wn * 32 + nt * 8 + (lane & 3) * 2;
            float b0 = 0.f, b1 = 0.f;
            if (BIAS) { b0 = bias[col]; b1 = bias[col + 1]; }
#pragma unroll
            for (int hh = 0; hh < 2; hh++) {
                int r = r0 + hh * 8;
                if (r >= M) continue;
                float v0 = acc[mt][nt][hh * 2 + 0];
                float v1 = acc[mt][nt][hh * 2 + 1];
                if (BIAS) { v0 += b0; v1 += b1; }
                if (RELU) { v0 = fmaxf(v0, 0.f); v1 = fmaxf(v1, 0.f); }
                *(float2*)&C[(size_t)r * 256 + col] = make_float2(v0, v1);
            }
        }
    }
}

// ============================================================
// CSR build (edge_index INT32: src = ei[e], dst = ei[E+e])
// ============================================================
__global__ void zero_int_kernel() {
    int i = blockIdx.x * blockDim.x + threadIdx.x;
    if (i < NN) { g_degi[i] = 0; g_cursor[i] = 0; }
}
__global__ void deg_count_kernel(const int* __restrict__ ei, int E) {
    int e = blockIdx.x * blockDim.x + threadIdx.x;
    if (e < E) {
        int d = ei[E + e];
        if ((unsigned)d < (unsigned)NN) atomicAdd(&g_degi[d], 1);
    }
}
__global__ void dinv_kernel() {
    int i = blockIdx.x * blockDim.x + threadIdx.x;
    if (i < NN) g_dinv[i] = rsqrtf((float)g_degi[i] + 1.0f);
}

// exclusive scan of g_degi -> g_rowstart (3 kernels)
__global__ void scan1_kernel() {
    __shared__ int sh[256];
    int t = threadIdx.x;
    int i = blockIdx.x * 256 + t;
    int v = (i < NN) ? g_degi[i] : 0;
    sh[t] = v;
    __syncthreads();
#pragma unroll
    for (int off = 1; off < 256; off <<= 1) {
        int x = (t >= off) ? sh[t - off] : 0;
        __syncthreads();
        sh[t] += x;
        __syncthreads();
    }
    if (i < NN) g_rowstart[i] = sh[t] - v;   // exclusive within block
    if (t == 255) g_blocksum[blockIdx.x] = sh[255];
}
__global__ void scan2_kernel() {
    __shared__ int sh[256];
    int t = threadIdx.x;
    int v = (t < NBLK) ? g_blocksum[t] : 0;
    sh[t] = v;
    __syncthreads();
#pragma unroll
    for (int off = 1; off < 256; off <<= 1) {
        int x = (t >= off) ? sh[t - off] : 0;
        __syncthreads();
        sh[t] += x;
        __syncthreads();
    }
    if (t < NBLK) g_blocksum[t] = sh[t] - v;  // exclusive block offsets
}
__global__ void scan3_kernel() {
    int i = blockIdx.x * blockDim.x + threadIdx.x;
    if (i < NN) g_rowstart[i] += g_blocksum[i >> 8];
}
__global__ void fill_csr_kernel(const int* __restrict__ ei, int E) {
    int e = blockIdx.x * blockDim.x + threadIdx.x;
    if (e >= E) return;
    int s = ei[e];
    int d = ei[E + e];
    if ((unsigned)s >= (unsigned)NN || (unsigned)d >= (unsigned)NN) return;
    int pos = g_rowstart[d] + atomicAdd(&g_cursor[d], 1);
    if (pos < EMAXC) g_esrc[pos] = s;
}

// ============================================================
// fused gather: h[d] = relu( sum_{s in N(d)} hW[s]*dinv[s]*dinv[d]
//                            + hW[d]*dinv[d]^2 + bias )
// one warp per destination node
// ============================================================
__global__ void gather_kernel(const float* __restrict__ hW,
                              const float* __restrict__ bias,
                              float* __restrict__ hout)
{
    int node = (blockIdx.x * blockDim.x + threadIdx.x) >> 5;
    int lane = threadIdx.x & 31;
    if (node >= NN) return;
    float dv = g_dinv[node];
    int base = g_rowstart[node];
    int cnt = g_degi[node];

    const float4* sp = (const float4*)(hW + (size_t)node * HH);
    float4 a0 = sp[lane];
    float4 a1 = sp[lane + 32];
    float ss = dv * dv;
    a0.x *= ss; a0.y *= ss; a0.z *= ss; a0.w *= ss;
    a1.x *= ss; a1.y *= ss; a1.z *= ss; a1.w *= ss;

    for (int j = 0; j < cnt; j++) {
        int s = g_esrc[base + j];
        float w = g_dinv[s] * dv;
        const float4* q = (const float4*)(hW + (size_t)s * HH);
        float4 v0 = q[lane];
        float4 v1 = q[lane + 32];
        a0.x += v0.x * w; a0.y += v0.y * w; a0.z += v0.z * w; a0.w += v0.w * w;
        a1.x += v1.x * w; a1.y += v1.y * w; a1.z += v1.z * w; a1.w += v1.w * w;
    }

    float4 b0 = ((const float4*)bias)[lane];
    float4 b1 = ((const float4*)bias)[lane + 32];
    a0.x = fmaxf(a0.x + b0.x, 0.f); a0.y = fmaxf(a0.y + b0.y, 0.f);
    a0.z = fmaxf(a0.z + b0.z, 0.f); a0.w = fmaxf(a0.w + b0.w, 0.f);
    a1.x = fmaxf(a1.x + b1.x, 0.f); a1.y = fmaxf(a1.y + b1.y, 0.f);
    a1.z = fmaxf(a1.z + b1.z, 0.f); a1.w = fmaxf(a1.w + b1.w, 0.f);

    float4* op = (float4*)(hout + (size_t)node * HH);
    op[lane] = a0;
    op[lane + 32] = a1;
}

// ============================================================
// softmax per row, one warp per row
// ============================================================
__global__ void softmax_kernel(const float* __restrict__ in, float* __restrict__ out) {
    int warp = (blockIdx.x * blockDim.x + threadIdx.x) >> 5;
    int lane = threadIdx.x & 31;
    if (warp >= NN) return;
    const float4* ip = (const float4*)(in + (size_t)warp * DOUT);
    float4 a = ip[lane];
    float4 b = ip[lane + 32];
    float m = fmaxf(fmaxf(fmaxf(a.x, a.y), fmaxf(a.z, a.w)),
                    fmaxf(fmaxf(b.x, b.y), fmaxf(b.z, b.w)));
#pragma unroll
    for (int o = 16; o > 0; o >>= 1)
        m = fmaxf(m, __shfl_xor_sync(0xFFFFFFFFu, m, o));
    a.x = __expf(a.x - m); a.y = __expf(a.y - m); a.z = __expf(a.z - m); a.w = __expf(a.w - m);
    b.x = __expf(b.x - m); b.y = __expf(b.y - m); b.z = __expf(b.z - m); b.w = __expf(b.w - m);
    float s = a.x + a.y + a.z + a.w + b.x + b.y + b.z + b.w;
#pragma unroll
    for (int o = 16; o > 0; o >>= 1)
        s += __shfl_xor_sync(0xFFFFFFFFu, s, o);
    float inv = 1.0f / s;
    a.x *= inv; a.y *= inv; a.z *= inv; a.w *= inv;
    b.x *= inv; b.y *= inv; b.z *= inv; b.w *= inv;
    float4* op = (float4*)(out + (size_t)warp * DOUT);
    op[lane] = a;
    op[lane + 32] = b;
}

// ============================================================
// host launch
// ============================================================
extern "C" void kernel_launch(void* const* d_in, const int* in_sizes, int n_in,
                              void* d_out, int out_size)
{
    const float* x    = (const float*)d_in[0];
    const int* ei     = (const int*)d_in[1];   // int32
    const float* W1  = (const float*)d_in[2];
    const float* b1  = (const float*)d_in[3];
    const float* Wg1 = (const float*)d_in[4];
    const float* bg1 = (const float*)d_in[5];
    const float* Wg2 = (const float*)d_in[6];
    const float* bg2 = (const float*)d_in[7];
    const float* W2  = (const float*)d_in[8];
    const float* b2  = (const float*)d_in[9];
    const float* W3  = (const float*)d_in[10];
    const float* b3  = (const float*)d_in[11];
    float* out = (float*)d_out;

    int E = in_sizes[1] / 2;

    float *h, *hW, *agg;
    unsigned char *ph, *pl;
    cudaGetSymbolAddress((void**)&h, g_h);
    cudaGetSymbolAddress((void**)&hW, g_hW);
    cudaGetSymbolAddress((void**)&agg, g_agg);
    cudaGetSymbolAddress((void**)&ph, g_packh);
    cudaGetSymbolAddress((void**)&pl, g_packl);

    dim3 gemmGrid((NN + 127) / 128, 2);
    const int NODE_WARPS = (NN * 32 + 255) / 256;

    // 1: pack weights
    {
        dim3 pg((256 * 256 + 255) / 256, 5);
        pack_weights_kernel<<<pg, 256>>>(W1, Wg1, Wg2, W2, W3);
    }
    // 2-5: degree + dinv + scan start
    zero_int_kernel<<<NBLK, 256>>>();
    deg_count_kernel<<<(E + 255) / 256, 256>>>(ei, E);
    dinv_kernel<<<NBLK, 256>>>();
    scan1_kernel<<<NBLK, 256>>>();

    // 6: layer 1 — h = relu(x @ W1 + b1)   [profiled launch]
    hmma_gemm_kernel<true, true><<<gemmGrid, 256>>>(
        x, ph + 0 * WPACK, pl + 0 * WPACK, b1, h, NN, DIN);

    // finish CSR
    scan2_kernel<<<1, 256>>>();
    scan3_kernel<<<NBLK, 256>>>();
    fill_csr_kernel<<<(E + 255) / 256, 256>>>(ei, E);

    // conv 1
    hmma_gemm_kernel<false, false><<<gemmGrid, 256>>>(
        h, ph + 1 * WPACK, pl + 1 * WPACK, nullptr, hW, NN, HH);
    gather_kernel<<<NODE_WARPS, 256>>>(hW, bg1, h);

    // conv 2
    hmma_gemm_kernel<false, false><<<gemmGrid, 256>>>(
        h, ph + 2 * WPACK, pl + 2 * WPACK, nullptr, hW, NN, HH);
    gather_kernel<<<NODE_WARPS, 256>>>(hW, bg2, h);

    // layer 4: hW = relu(h @ W2 + b2)
    hmma_gemm_kernel<true, true><<<gemmGrid, 256>>>(
        h, ph + 3 * WPACK, pl + 3 * WPACK, b2, hW, NN, HH);

    // layer 5 logits: agg = hW @ W3 + b3
    hmma_gemm_kernel<true, false><<<gemmGrid, 256>>>(
        hW, ph + 4 * WPACK, pl + 4 * WPACK, b3, agg, NN, HH);

    // softmax -> out
    softmax_kernel<<<(NN * 32 + 255) / 256, 256>>>(agg, out);
}

// round 11
// speedup vs baseline: 2.3039x; 1.0804x over previous
#include <cuda_runtime.h>
#include <cuda_bf16.h>
#include <math.h>

#define NN 50000
#define DIN 128
#define HH 256
#define DOUT 256
#define NBLK 196          // ceil(NN/256)
#define EMAXC 320000

// ---- scratch (device globals; no allocation allowed) ----
__device__ float g_h[NN * HH];
__device__ float g_hW[NN * HH];
__device__ float g_agg[NN * HH];
__device__ float g_dinv[NN];
__device__ int   g_degi[NN];
__device__ int   g_cursor[NN];
__device__ int   g_rowstart[NN];
__device__ int   g_esrc[EMAXC];
__device__ int   g_blocksum[256];

// packed weights: per weight/term: [nh 2][chunk K/32][8KB: n 128 rows x 32 bf16, swizzled]
#define WPACK 131072
__device__ __align__(16) unsigned char g_packh[5 * WPACK];
__device__ __align__(16) unsigned char g_packl[5 * WPACK];

// ============================================================
// mma.sync m16n8k16 bf16 (row.col), fp32 accum + ldmatrix
// ============================================================
__device__ __forceinline__ void mma16816(float* c, const unsigned* a, const unsigned* b) {
    asm volatile(
        "mma.sync.aligned.m16n8k16.row.col.f32.bf16.bf16.f32 "
        "{%0,%1,%2,%3}, {%4,%5,%6,%7}, {%8,%9}, {%0,%1,%2,%3};"
        : "+f"(c[0]), "+f"(c[1]), "+f"(c[2]), "+f"(c[3])
        : "r"(a[0]), "r"(a[1]), "r"(a[2]), "r"(a[3]), "r"(b[0]), "r"(b[1]));
}
__device__ __forceinline__ void ldsm4(unsigned* r, unsigned addr) {
    asm volatile("ldmatrix.sync.aligned.m8n8.x4.shared.b16 {%0,%1,%2,%3}, [%4];"
                 : "=r"(r[0]), "=r"(r[1]), "=r"(r[2]), "=r"(r[3]) : "r"(addr));
}
__device__ __forceinline__ unsigned pack_bf2(__nv_bfloat16 x, __nv_bfloat16 y) {
    return ((unsigned)__bfloat16_as_ushort(y) << 16) | __bfloat16_as_ushort(x);
}
// swizzled byte offset within an 8KB tile: row (0..127) of 64B, granule g (0..3), byte b (0..15)
__device__ __host__ __forceinline__ int swz_off(int row, int g, int b) {
    return row * 64 + ((g ^ ((row >> 1) & 3)) << 4) + b;
}

// ============================================================
// weight prepack: W[K,256] fp32 -> hi/lo bf16 in ldmatrix-ready [n][k] swizzled tiles
// ============================================================
__global__ void pack_weights_kernel(const float* W1, const float* Wg1, const float* Wg2,
                                    const float* W2, const float* W3) {
    int wi = blockIdx.y;
    const float* W = (wi == 0) ? W1 : (wi == 1) ? Wg1 : (wi == 2) ? Wg2 : (wi == 3) ? W2 : W3;
    int K = (wi == 0) ? DIN : HH;
    int i = blockIdx.x * blockDim.x + threadIdx.x;
    if (i >= K * 256) return;
    int k = i >> 8, n = i & 255;
    float w = W[i];
    __nv_bfloat16 h = __float2bfloat16(w);
    __nv_bfloat16 l = __float2bfloat16(w - __bfloat162float(h));
    int c = k >> 5, kl = k & 31;
    int kp = kl >> 1, hl = kl & 1;
    int nh = n >> 7, nl = n & 127;
    size_t off = (size_t)wi * WPACK + ((size_t)(nh * (K >> 5) + c)) * 8192
               + swz_off(nl, kp >> 2, (kp & 3) * 4 + hl * 2);
    *(__nv_bfloat16*)(g_packh + off) = h;
    *(__nv_bfloat16*)(g_packl + off) = l;
}

// ============================================================
// HMMA GEMM: C[M,256] = A[M,K] @ W (+bias)(relu)
// CTA 128 rows x 128 cols (grid.y = col half), 8 warps (2M x 4N), warp m64n32.
// BK=32, ldmatrix fragment loads, bf16 2-term split (3 products).
// ============================================================
template <bool BIAS, bool RELU>
__global__ __launch_bounds__(256, 1) void hmma_gemm_kernel(
    const float* __restrict__ A, const unsigned char* __restrict__ Bhp,
    const unsigned char* __restrict__ Blp, const float* __restrict__ bias,
    float* __restrict__ C, int M, int K)
{
    __shared__ __align__(16) unsigned char Ahs[8192];
    __shared__ __align__(16) unsigned char Als[8192];
    __shared__ __align__(16) unsigned char Bhs[8192];
    __shared__ __align__(16) unsigned char Bls[8192];

    int tid = threadIdx.x;
    int lane = tid & 31;
    int wid = tid >> 5;
    int wm = wid & 1;
    int wn = wid >> 1;
    int row0 = blockIdx.x * 128;
    int colBlock = blockIdx.y * 128;
    int chunks = K >> 5;

    const unsigned char* Bhg = Bhp + (size_t)blockIdx.y * chunks * 8192;
    const unsigned char* Blg = Blp + (size_t)blockIdx.y * chunks * 8192;

    unsigned baseAh = (unsigned)__cvta_generic_to_shared(Ahs);
    unsigned baseAl = (unsigned)__cvta_generic_to_shared(Als);
    unsigned baseBh = (unsigned)__cvta_generic_to_shared(Bhs);
    unsigned baseBl = (unsigned)__cvta_generic_to_shared(Bls);

    // precompute per-lane ldmatrix offsets (j=0; j=1 differs by ^32)
    unsigned offA[4], offB[2];
    {
        int rA = wm * 64 + (lane & 15);
        int gA = lane >> 4;                  // 0..1
#pragma unroll
        for (int mt = 0; mt < 4; mt++) {
            int r = rA + mt * 16;
            offA[mt] = swz_off(r, gA, 0);
        }
        int nB = wn * 32 + ((lane >> 4) << 3) + (lane & 7);
        int gB = (lane >> 3) & 1;
#pragma unroll
        for (int np = 0; np < 2; np++) {
            int n = nB + np * 16;
            offB[np] = swz_off(n, gB, 0);
        }
    }

    float acc[4][4][4];
#pragma unroll
    for (int mt = 0; mt < 4; mt++)
#pragma unroll
        for (int nt = 0; nt < 4; nt++)
#pragma unroll
            for (int q = 0; q < 4; q++) acc[mt][nt][q] = 0.0f;

    for (int c = 0; c < chunks; c++) {
        // ---- stage A: 128 rows x 16 k-pairs, fp32 -> hi/lo bf16x2, swizzled ----
#pragma unroll
        for (int it = 0; it < 8; it++) {
            int slot = tid + it * 256;       // 0..2047
            int kp = slot & 15;
            int r = slot >> 4;
            int grow = row0 + r;
            float2 v = make_float2(0.f, 0.f);
            if (grow < M)
                v = *(const float2*)&A[(size_t)grow * K + c * 32 + kp * 2];
            __nv_bfloat16 h0 = __float2bfloat16(v.x), h1 = __float2bfloat16(v.y);
            __nv_bfloat16 l0 = __float2bfloat16(v.x - __bfloat162float(h0));
            __nv_bfloat16 l1 = __float2bfloat16(v.y - __bfloat162float(h1));
            int off = swz_off(r, kp >> 2, (kp & 3) * 4);
            *(unsigned*)(Ahs + off) = pack_bf2(h0, h1);
            *(unsigned*)(Als + off) = pack_bf2(l0, l1);
        }
        // ---- stage B: linear copy of pre-swizzled 8KB blocks ----
        {
            const uint4* sh = (const uint4*)(Bhg + (size_t)c * 8192);
            const uint4* sl = (const uint4*)(Blg + (size_t)c * 8192);
#pragma unroll
            for (int it = 0; it < 2; it++) {
                int i = tid + it * 256;      // 0..511 uint4
                ((uint4*)Bhs)[i] = sh[i];
                ((uint4*)Bls)[i] = sl[i];
            }
        }
        __syncthreads();

#pragma unroll
        for (int j = 0; j < 2; j++) {
            unsigned jx = j ? 32u : 0u;
            unsigned bfh[2][4], bfl[2][4];   // [np]{b0 nt0, b1 nt0, b0 nt1, b1 nt1}
#pragma unroll
            for (int np = 0; np < 2; np++) {
                ldsm4(bfh[np], baseBh + (offB[np] ^ jx));
                ldsm4(bfl[np], baseBl + (offB[np] ^ jx));
            }
            unsigned afh[4][4], afl[4][4];
#pragma unroll
            for (int mt = 0; mt < 4; mt++) {
                ldsm4(afh[mt], baseAh + (offA[mt] ^ jx));
                ldsm4(afl[mt], baseAl + (offA[mt] ^ jx));
            }
#pragma unroll
            for (int mt = 0; mt < 4; mt++)
#pragma unroll
                for (int nt = 0; nt < 4; nt++) {
                    const unsigned* bh = &bfh[nt >> 1][(nt & 1) * 2];
                    const unsigned* bl = &bfl[nt >> 1][(nt & 1) * 2];
                    mma16816(acc[mt][nt], afh[mt], bh);
                    mma16816(acc[mt][nt], afh[mt], bl);
                    mma16816(acc[mt][nt], afl[mt], bh);
                }
        }
        __syncthreads();
    }

    // ---- epilogue ----
#pragma unroll
    for (int mt = 0; mt < 4; mt++) {
        int r0 = row0 + wm * 64 + mt * 16 + (lane >> 2);
#pragma unroll
        for (int nt = 0; nt < 4; nt++) {
            int col = colBlock + wn * 32 + nt * 8 + (lane & 3) * 2;
            float b0 = 0.f, b1 = 0.f;
            if (BIAS) { b0 = bias[col]; b1 = bias[col + 1]; }
#pragma unroll
            for (int hh = 0; hh < 2; hh++) {
                int r = r0 + hh * 8;
                if (r >= M) continue;
                float v0 = acc[mt][nt][hh * 2 + 0];
                float v1 = acc[mt][nt][hh * 2 + 1];
                if (BIAS) { v0 += b0; v1 += b1; }
                if (RELU) { v0 = fmaxf(v0, 0.f); v1 = fmaxf(v1, 0.f); }
                *(float2*)&C[(size_t)r * 256 + col] = make_float2(v0, v1);
            }
        }
    }
}

// ============================================================
// CSR build (edge_index INT32: src = ei[e], dst = ei[E+e])
// ============================================================
__global__ void zero_int_kernel() {
    int i = blockIdx.x * blockDim.x + threadIdx.x;
    if (i < NN) { g_degi[i] = 0; g_cursor[i] = 0; }
}
__global__ void deg_count_kernel(const int* __restrict__ ei, int E) {
    int e = blockIdx.x * blockDim.x + threadIdx.x;
    if (e < E) {
        int d = ei[E + e];
        if ((unsigned)d < (unsigned)NN) atomicAdd(&g_degi[d], 1);
    }
}
__global__ void dinv_kernel() {
    int i = blockIdx.x * blockDim.x + threadIdx.x;
    if (i < NN) g_dinv[i] = rsqrtf((float)g_degi[i] + 1.0f);
}
__global__ void scan1_kernel() {
    __shared__ int sh[256];
    int t = threadIdx.x;
    int i = blockIdx.x * 256 + t;
    int v = (i < NN) ? g_degi[i] : 0;
    sh[t] = v;
    __syncthreads();
#pragma unroll
    for (int off = 1; off < 256; off <<= 1) {
        int x = (t >= off) ? sh[t - off] : 0;
        __syncthreads();
        sh[t] += x;
        __syncthreads();
    }
    if (i < NN) g_rowstart[i] = sh[t] - v;
    if (t == 255) g_blocksum[blockIdx.x] = sh[255];
}
__global__ void scan2_kernel() {
    __shared__ int sh[256];
    int t = threadIdx.x;
    int v = (t < NBLK) ? g_blocksum[t] : 0;
    sh[t] = v;
    __syncthreads();
#pragma unroll
    for (int off = 1; off < 256; off <<= 1) {
        int x = (t >= off) ? sh[t - off] : 0;
        __syncthreads();
        sh[t] += x;
        __syncthreads();
    }
    if (t < NBLK) g_blocksum[t] = sh[t] - v;
}
__global__ void scan3_kernel() {
    int i = blockIdx.x * blockDim.x + threadIdx.x;
    if (i < NN) g_rowstart[i] += g_blocksum[i >> 8];
}
__global__ void fill_csr_kernel(const int* __restrict__ ei, int E) {
    int e = blockIdx.x * blockDim.x + threadIdx.x;
    if (e >= E) return;
    int s = ei[e];
    int d = ei[E + e];
    if ((unsigned)s >= (unsigned)NN || (unsigned)d >= (unsigned)NN) return;
    int pos = g_rowstart[d] + atomicAdd(&g_cursor[d], 1);
    if (pos < EMAXC) g_esrc[pos] = s;
}

// ============================================================
// fused gather: h[d] = relu( sum hW[s]*dinv[s]*dinv[d] + hW[d]*dinv[d]^2 + bias )
// ============================================================
__global__ void gather_kernel(const float* __restrict__ hW,
                              const float* __restrict__ bias,
                              float* __restrict__ hout)
{
    int node = (blockIdx.x * blockDim.x + threadIdx.x) >> 5;
    int lane = threadIdx.x & 31;
    if (node >= NN) return;
    float dv = g_dinv[node];
    int base = g_rowstart[node];
    int cnt = g_degi[node];

    const float4* sp = (const float4*)(hW + (size_t)node * HH);
    float4 a0 = sp[lane];
    float4 a1 = sp[lane + 32];
    float ss = dv * dv;
    a0.x *= ss; a0.y *= ss; a0.z *= ss; a0.w *= ss;
    a1.x *= ss; a1.y *= ss; a1.z *= ss; a1.w *= ss;

    for (int j = 0; j < cnt; j++) {
        int s = g_esrc[base + j];
        float w = g_dinv[s] * dv;
        const float4* q = (const float4*)(hW + (size_t)s * HH);
        float4 v0 = q[lane];
        float4 v1 = q[lane + 32];
        a0.x += v0.x * w; a0.y += v0.y * w; a0.z += v0.z * w; a0.w += v0.w * w;
        a1.x += v1.x * w; a1.y += v1.y * w; a1.z += v1.z * w; a1.w += v1.w * w;
    }

    float4 b0 = ((const float4*)bias)[lane];
    float4 b1 = ((const float4*)bias)[lane + 32];
    a0.x = fmaxf(a0.x + b0.x, 0.f); a0.y = fmaxf(a0.y + b0.y, 0.f);
    a0.z = fmaxf(a0.z + b0.z, 0.f); a0.w = fmaxf(a0.w + b0.w, 0.f);
    a1.x = fmaxf(a1.x + b1.x, 0.f); a1.y = fmaxf(a1.y + b1.y, 0.f);
    a1.z = fmaxf(a1.z + b1.z, 0.f); a1.w = fmaxf(a1.w + b1.w, 0.f);

    float4* op = (float4*)(hout + (size_t)node * HH);
    op[lane] = a0;
    op[lane + 32] = a1;
}

// ============================================================
// softmax per row, one warp per row
// ============================================================
__global__ void softmax_kernel(const float* __restrict__ in, float* __restrict__ out) {
    int warp = (blockIdx.x * blockDim.x + threadIdx.x) >> 5;
    int lane = threadIdx.x & 31;
    if (warp >= NN) return;
    const float4* ip = (const float4*)(in + (size_t)warp * DOUT);
    float4 a = ip[lane];
    float4 b = ip[lane + 32];
    float m = fmaxf(fmaxf(fmaxf(a.x, a.y), fmaxf(a.z, a.w)),
                    fmaxf(fmaxf(b.x, b.y), fmaxf(b.z, b.w)));
#pragma unroll
    for (int o = 16; o > 0; o >>= 1)
        m = fmaxf(m, __shfl_xor_sync(0xFFFFFFFFu, m, o));
    a.x = __expf(a.x - m); a.y = __expf(a.y - m); a.z = __expf(a.z - m); a.w = __expf(a.w - m);
    b.x = __expf(b.x - m); b.y = __expf(b.y - m); b.z = __expf(b.z - m); b.w = __expf(b.w - m);
    float s = a.x + a.y + a.z + a.w + b.x + b.y + b.z + b.w;
#pragma unroll
    for (int o = 16; o > 0; o >>= 1)
        s += __shfl_xor_sync(0xFFFFFFFFu, s, o);
    float inv = 1.0f / s;
    a.x *= inv; a.y *= inv; a.z *= inv; a.w *= inv;
    b.x *= inv; b.y *= inv; b.z *= inv; b.w *= inv;
    float4* op = (float4*)(out + (size_t)warp * DOUT);
    op[lane] = a;
    op[lane + 32] = b;
}

// ============================================================
// host launch
// ============================================================
extern "C" void kernel_launch(void* const* d_in, const int* in_sizes, int n_in,
                              void* d_out, int out_size)
{
    const float* x    = (const float*)d_in[0];
    const int* ei     = (const int*)d_in[1];   // int32
    const float* W1  = (const float*)d_in[2];
    const float* b1  = (const float*)d_in[3];
    const float* Wg1 = (const float*)d_in[4];
    const float* bg1 = (const float*)d_in[5];
    const float* Wg2 = (const float*)d_in[6];
    const float* bg2 = (const float*)d_in[7];
    const float* W2  = (const float*)d_in[8];
    const float* b2  = (const float*)d_in[9];
    const float* W3  = (const float*)d_in[10];
    const float* b3  = (const float*)d_in[11];
    float* out = (float*)d_out;

    int E = in_sizes[1] / 2;

    float *h, *hW, *agg;
    unsigned char *ph, *pl;
    cudaGetSymbolAddress((void**)&h, g_h);
    cudaGetSymbolAddress((void**)&hW, g_hW);
    cudaGetSymbolAddress((void**)&agg, g_agg);
    cudaGetSymbolAddress((void**)&ph, g_packh);
    cudaGetSymbolAddress((void**)&pl, g_packl);

    dim3 gemmGrid((NN + 127) / 128, 2);
    const int NODE_WARPS = (NN * 32 + 255) / 256;

    // pack weights
    {
        dim3 pg((256 * 256 + 255) / 256, 5);
        pack_weights_kernel<<<pg, 256>>>(W1, Wg1, Wg2, W2, W3);
    }
    // degrees + dinv + scan
    zero_int_kernel<<<NBLK, 256>>>();
    deg_count_kernel<<<(E + 255) / 256, 256>>>(ei, E);
    dinv_kernel<<<NBLK, 256>>>();
    scan1_kernel<<<NBLK, 256>>>();

    // layer 1: h = relu(x @ W1 + b1)
    hmma_gemm_kernel<true, true><<<gemmGrid, 256>>>(
        x, ph + 0 * WPACK, pl + 0 * WPACK, b1, h, NN, DIN);

    // finish CSR
    scan2_kernel<<<1, 256>>>();
    scan3_kernel<<<NBLK, 256>>>();
    fill_csr_kernel<<<(E + 255) / 256, 256>>>(ei, E);

    // conv 1
    hmma_gemm_kernel<false, false><<<gemmGrid, 256>>>(
        h, ph + 1 * WPACK, pl + 1 * WPACK, nullptr, hW, NN, HH);
    gather_kernel<<<NODE_WARPS, 256>>>(hW, bg1, h);

    // conv 2
    hmma_gemm_kernel<false, false><<<gemmGrid, 256>>>(
        h, ph + 2 * WPACK, pl + 2 * WPACK, nullptr, hW, NN, HH);
    gather_kernel<<<NODE_WARPS, 256>>>(hW, bg2, h);

    // layer 4: hW = relu(h @ W2 + b2)
    hmma_gemm_kernel<true, true><<<gemmGrid, 256>>>(
        h, ph + 3 * WPACK, pl + 3 * WPACK, b2, hW, NN, HH);

    // layer 5 logits: agg = hW @ W3 + b3
    hmma_gemm_kernel<true, false><<<gemmGrid, 256>>>(
        hW, ph + 4 * WPACK, pl + 4 * WPACK, b3, agg, NN, HH);

    // softmax -> out
    softmax_kernel<<<(NN * 32 + 255) / 256, 256>>>(agg, out);
}

// round 12
// speedup vs baseline: 2.7311x; 1.1854x over previous
#include <cuda_runtime.h>
#include <cuda_bf16.h>
#include <math.h>

#define NN 50000
#define DIN 128
#define HH 256
#define DOUT 256
#define NBLK 196          // ceil(NN/256)
#define EMAXC 320000

// ---- scratch (device globals; no allocation allowed) ----
__device__ float g_h[NN * HH];
__device__ float g_hW[NN * HH];
__device__ float g_agg[NN * HH];
__device__ float g_dinv[NN];
__device__ int   g_degi[NN];
__device__ int   g_cursor[NN];
__device__ int   g_rowstart[NN];
__device__ int   g_esrc[EMAXC];
__device__ int   g_blocksum[256];

// packed weights: per weight/term: [nh 2][chunk K/32][8KB: n 128 rows x 32 bf16, swizzled]
#define WPACK 131072
__device__ __align__(16) unsigned char g_packh[5 * WPACK];
__device__ __align__(16) unsigned char g_packl[5 * WPACK];

// ============================================================
// mma.sync m16n8k16 bf16 (row.col), fp32 accum + ldmatrix + cp.async
// ============================================================
__device__ __forceinline__ void mma16816(float* c, const unsigned* a, const unsigned* b) {
    asm volatile(
        "mma.sync.aligned.m16n8k16.row.col.f32.bf16.bf16.f32 "
        "{%0,%1,%2,%3}, {%4,%5,%6,%7}, {%8,%9}, {%0,%1,%2,%3};"
        : "+f"(c[0]), "+f"(c[1]), "+f"(c[2]), "+f"(c[3])
        : "r"(a[0]), "r"(a[1]), "r"(a[2]), "r"(a[3]), "r"(b[0]), "r"(b[1]));
}
__device__ __forceinline__ void ldsm4(unsigned* r, unsigned addr) {
    asm volatile("ldmatrix.sync.aligned.m8n8.x4.shared.b16 {%0,%1,%2,%3}, [%4];"
                 : "=r"(r[0]), "=r"(r[1]), "=r"(r[2]), "=r"(r[3]) : "r"(addr));
}
__device__ __forceinline__ void cpasync16(unsigned saddr, const void* gaddr) {
    asm volatile("cp.async.cg.shared.global [%0], [%1], 16;" :: "r"(saddr), "l"(gaddr));
}
__device__ __forceinline__ void cpcommit() { asm volatile("cp.async.commit_group;"); }
__device__ __forceinline__ void cpwait0() { asm volatile("cp.async.wait_group 0;" ::: "memory"); }

__device__ __forceinline__ unsigned pack_bf2(__nv_bfloat16 x, __nv_bfloat16 y) {
    return ((unsigned)__bfloat16_as_ushort(y) << 16) | __bfloat16_as_ushort(x);
}
// swizzled byte offset within an 8KB tile: row (0..127) of 64B, granule g (0..3), byte b (0..15)
__device__ __host__ __forceinline__ int swz_off(int row, int g, int b) {
    return row * 64 + ((g ^ ((row >> 1) & 3)) << 4) + b;
}

// ============================================================
// weight prepack: W[K,256] fp32 -> hi/lo bf16 in ldmatrix-ready [n][k] swizzled tiles
// ============================================================
__global__ void pack_weights_kernel(const float* W1, const float* Wg1, const float* Wg2,
                                    const float* W2, const float* W3) {
    int wi = blockIdx.y;
    const float* W = (wi == 0) ? W1 : (wi == 1) ? Wg1 : (wi == 2) ? Wg2 : (wi == 3) ? W2 : W3;
    int K = (wi == 0) ? DIN : HH;
    int i = blockIdx.x * blockDim.x + threadIdx.x;
    if (i >= K * 256) return;
    int k = i >> 8, n = i & 255;
    float w = W[i];
    __nv_bfloat16 h = __float2bfloat16(w);
    __nv_bfloat16 l = __float2bfloat16(w - __bfloat162float(h));
    int c = k >> 5, kl = k & 31;
    int kp = kl >> 1, hl = kl & 1;
    int nh = n >> 7, nl = n & 127;
    size_t off = (size_t)wi * WPACK + ((size_t)(nh * (K >> 5) + c)) * 8192
               + swz_off(nl, kp >> 2, (kp & 3) * 4 + hl * 2);
    *(__nv_bfloat16*)(g_packh + off) = h;
    *(__nv_bfloat16*)(g_packl + off) = l;
}

// ============================================================
// HMMA GEMM, double-buffered + cp.async pipeline.
// C[M,256] = A[M,K] @ W (+bias)(relu)
// CTA 128x128 (grid.y = col half), 8 warps (2M x 4N), warp m64n32, BK=32.
// dynamic smem: 2 bufs x {Ah,Al,Bh,Bl} x 8KB = 64KB
// ============================================================
#define BUF 32768
#define OAH 0
#define OAL 8192
#define OBH 16384
#define OBL 24576

template <bool BIAS, bool RELU>
__global__ __launch_bounds__(256, 1) void hmma_gemm_kernel(
    const float* __restrict__ A, const unsigned char* __restrict__ Bhp,
    const unsigned char* __restrict__ Blp, const float* __restrict__ bias,
    float* __restrict__ C, int M, int K)
{
    extern __shared__ __align__(16) unsigned char smem[];
    unsigned sbase = (unsigned)__cvta_generic_to_shared(smem);

    int tid = threadIdx.x;
    int lane = tid & 31;
    int wid = tid >> 5;
    int wm = wid & 1;
    int wn = wid >> 1;
    int row0 = blockIdx.x * 128;
    int colBlock = blockIdx.y * 128;
    int chunks = K >> 5;

    const unsigned char* Bhg = Bhp + (size_t)blockIdx.y * chunks * 8192;
    const unsigned char* Blg = Blp + (size_t)blockIdx.y * chunks * 8192;

    // A staging geometry (per thread, 8 slots)
    int skp = tid & 15;          // k-pair 0..15
    int srow = tid >> 4;         // base row 0..15 (+16 per it)
    int sAoff[8];
    bool sOK[8];
#pragma unroll
    for (int it = 0; it < 8; it++) {
        int r = srow + it * 16;
        sAoff[it] = swz_off(r, skp >> 2, (skp & 3) * 4);
        sOK[it] = (row0 + r) < M;
    }

    // B cp.async geometry: 2 x 16B per term per thread
    unsigned bso0 = tid * 16, bso1 = (tid + 256) * 16;

    // ldmatrix offsets (j=0; j=1 differs by ^32)
    unsigned offA[4], offB[2];
    {
        int rA = wm * 64 + (lane & 15);
        int gA = lane >> 4;
#pragma unroll
        for (int mt = 0; mt < 4; mt++) offA[mt] = swz_off(rA + mt * 16, gA, 0);
        int nB = wn * 32 + ((lane >> 4) << 3) + (lane & 7);
        int gB = (lane >> 3) & 1;
#pragma unroll
        for (int np = 0; np < 2; np++) offB[np] = swz_off(nB + np * 16, gB, 0);
    }

    float acc[4][4][4];
#pragma unroll
    for (int mt = 0; mt < 4; mt++)
#pragma unroll
        for (int nt = 0; nt < 4; nt++)
#pragma unroll
            for (int q = 0; q < 4; q++) acc[mt][nt][q] = 0.0f;

    // ---- prologue: stage chunk 0 into buf 0 ----
    {
#pragma unroll
        for (int it = 0; it < 8; it++) {
            int r = srow + it * 16;
            float2 v = make_float2(0.f, 0.f);
            if (sOK[it]) v = *(const float2*)&A[(size_t)(row0 + r) * K + skp * 2];
            __nv_bfloat16 h0 = __float2bfloat16(v.x), h1 = __float2bfloat16(v.y);
            __nv_bfloat16 l0 = __float2bfloat16(v.x - __bfloat162float(h0));
            __nv_bfloat16 l1 = __float2bfloat16(v.y - __bfloat162float(h1));
            *(unsigned*)(smem + OAH + sAoff[it]) = pack_bf2(h0, h1);
            *(unsigned*)(smem + OAL + sAoff[it]) = pack_bf2(l0, l1);
        }
        cpasync16(sbase + OBH + bso0, Bhg + bso0);
        cpasync16(sbase + OBH + bso1, Bhg + bso1);
        cpasync16(sbase + OBL + bso0, Blg + bso0);
        cpasync16(sbase + OBL + bso1, Blg + bso1);
        cpcommit();
    }

    for (int c = 0; c < chunks; c++) {
        unsigned cb = (c & 1) * BUF;
        unsigned nb = ((c + 1) & 1) * BUF;
        bool more = (c + 1) < chunks;

        // prefetch A for next chunk into registers (overlaps wait + MMAs)
        float2 areg[8];
        if (more) {
#pragma unroll
            for (int it = 0; it < 8; it++) {
                int r = srow + it * 16;
                areg[it] = make_float2(0.f, 0.f);
                if (sOK[it])
                    areg[it] = *(const float2*)&A[(size_t)(row0 + r) * K + (c + 1) * 32 + skp * 2];
            }
        }

        cpwait0();
        __syncthreads();

        // kick off next B copy (overlaps MMAs below)
        if (more) {
            const unsigned char* bh = Bhg + (size_t)(c + 1) * 8192;
            const unsigned char* bl = Blg + (size_t)(c + 1) * 8192;
            cpasync16(sbase + nb + OBH + bso0, bh + bso0);
            cpasync16(sbase + nb + OBH + bso1, bh + bso1);
            cpasync16(sbase + nb + OBL + bso0, bl + bso0);
            cpasync16(sbase + nb + OBL + bso1, bl + bso1);
            cpcommit();
        }

        // ---- MMAs on current buffer ----
#pragma unroll
        for (int j = 0; j < 2; j++) {
            unsigned jx = j ? 32u : 0u;
            unsigned bfh[2][4], bfl[2][4];
#pragma unroll
            for (int np = 0; np < 2; np++) {
                ldsm4(bfh[np], sbase + cb + OBH + (offB[np] ^ jx));
                ldsm4(bfl[np], sbase + cb + OBL + (offB[np] ^ jx));
            }
            unsigned afh[4][4], afl[4][4];
#pragma unroll
            for (int mt = 0; mt < 4; mt++) {
                ldsm4(afh[mt], sbase + cb + OAH + (offA[mt] ^ jx));
                ldsm4(afl[mt], sbase + cb + OAL + (offA[mt] ^ jx));
            }
#pragma unroll
            for (int mt = 0; mt < 4; mt++)
#pragma unroll
                for (int nt = 0; nt < 4; nt++) {
                    const unsigned* bh = &bfh[nt >> 1][(nt & 1) * 2];
                    const unsigned* bl = &bfl[nt >> 1][(nt & 1) * 2];
                    mma16816(acc[mt][nt], afh[mt], bh);
                    mma16816(acc[mt][nt], afh[mt], bl);
                    mma16816(acc[mt][nt], afl[mt], bh);
                }
        }

        // convert + store prefetched A into next buffer
        if (more) {
#pragma unroll
            for (int it = 0; it < 8; it++) {
                float2 v = areg[it];
                __nv_bfloat16 h0 = __float2bfloat16(v.x), h1 = __float2bfloat16(v.y);
                __nv_bfloat16 l0 = __float2bfloat16(v.x - __bfloat162float(h0));
                __nv_bfloat16 l1 = __float2bfloat16(v.y - __bfloat162float(h1));
                *(unsigned*)(smem + nb + OAH + sAoff[it]) = pack_bf2(h0, h1);
                *(unsigned*)(smem + nb + OAL + sAoff[it]) = pack_bf2(l0, l1);
            }
        }
    }

    // ---- epilogue ----
#pragma unroll
    for (int mt = 0; mt < 4; mt++) {
        int r0 = row0 + wm * 64 + mt * 16 + (lane >> 2);
#pragma unroll
        for (int nt = 0; nt < 4; nt++) {
            int col = colBlock + wn * 32 + nt * 8 + (lane & 3) * 2;
            float b0 = 0.f, b1 = 0.f;
            if (BIAS) { b0 = bias[col]; b1 = bias[col + 1]; }
#pragma unroll
            for (int hh = 0; hh < 2; hh++) {
                int r = r0 + hh * 8;
                if (r >= M) continue;
                float v0 = acc[mt][nt][hh * 2 + 0];
                float v1 = acc[mt][nt][hh * 2 + 1];
                if (BIAS) { v0 += b0; v1 += b1; }
                if (RELU) { v0 = fmaxf(v0, 0.f); v1 = fmaxf(v1, 0.f); }
                *(float2*)&C[(size_t)r * 256 + col] = make_float2(v0, v1);
            }
        }
    }
}

// ============================================================
// CSR build (edge_index INT32: src = ei[e], dst = ei[E+e])
// ============================================================
__global__ void zero_int_kernel() {
    int i = blockIdx.x * blockDim.x + threadIdx.x;
    if (i < NN) { g_degi[i] = 0; g_cursor[i] = 0; }
}
__global__ void deg_count_kernel(const int* __restrict__ ei, int E) {
    int e = blockIdx.x * blockDim.x + threadIdx.x;
    if (e < E) {
        int d = ei[E + e];
        if ((unsigned)d < (unsigned)NN) atomicAdd(&g_degi[d], 1);
    }
}
__global__ void dinv_kernel() {
    int i = blockIdx.x * blockDim.x + threadIdx.x;
    if (i < NN) g_dinv[i] = rsqrtf((float)g_degi[i] + 1.0f);
}
__global__ void scan1_kernel() {
    __shared__ int sh[256];
    int t = threadIdx.x;
    int i = blockIdx.x * 256 + t;
    int v = (i < NN) ? g_degi[i] : 0;
    sh[t] = v;
    __syncthreads();
#pragma unroll
    for (int off = 1; off < 256; off <<= 1) {
        int x = (t >= off) ? sh[t - off] : 0;
        __syncthreads();
        sh[t] += x;
        __syncthreads();
    }
    if (i < NN) g_rowstart[i] = sh[t] - v;
    if (t == 255) g_blocksum[blockIdx.x] = sh[255];
}
__global__ void scan2_kernel() {
    __shared__ int sh[256];
    int t = threadIdx.x;
    int v = (t < NBLK) ? g_blocksum[t] : 0;
    sh[t] = v;
    __syncthreads();
#pragma unroll
    for (int off = 1; off < 256; off <<= 1) {
        int x = (t >= off) ? sh[t - off] : 0;
        __syncthreads();
        sh[t] += x;
        __syncthreads();
    }
    if (t < NBLK) g_blocksum[t] = sh[t] - v;
}
__global__ void scan3_kernel() {
    int i = blockIdx.x * blockDim.x + threadIdx.x;
    if (i < NN) g_rowstart[i] += g_blocksum[i >> 8];
}
__global__ void fill_csr_kernel(const int* __restrict__ ei, int E) {
    int e = blockIdx.x * blockDim.x + threadIdx.x;
    if (e >= E) return;
    int s = ei[e];
    int d = ei[E + e];
    if ((unsigned)s >= (unsigned)NN || (unsigned)d >= (unsigned)NN) return;
    int pos = g_rowstart[d] + atomicAdd(&g_cursor[d], 1);
    if (pos < EMAXC) g_esrc[pos] = s;
}

// ============================================================
// fused gather: h[d] = relu( sum hW[s]*dinv[s]*dinv[d] + hW[d]*dinv[d]^2 + bias )
// ============================================================
__global__ void gather_kernel(const float* __restrict__ hW,
                              const float* __restrict__ bias,
                              float* __restrict__ hout)
{
    int node = (blockIdx.x * blockDim.x + threadIdx.x) >> 5;
    int lane = threadIdx.x & 31;
    if (node >= NN) return;
    float dv = g_dinv[node];
    int base = g_rowstart[node];
    int cnt = g_degi[node];

    const float4* sp = (const float4*)(hW + (size_t)node * HH);
    float4 a0 = sp[lane];
    float4 a1 = sp[lane + 32];
    float ss = dv * dv;
    a0.x *= ss; a0.y *= ss; a0.z *= ss; a0.w *= ss;
    a1.x *= ss; a1.y *= ss; a1.z *= ss; a1.w *= ss;

    for (int j = 0; j < cnt; j++) {
        int s = g_esrc[base + j];
        float w = g_dinv[s] * dv;
        const float4* q = (const float4*)(hW + (size_t)s * HH);
        float4 v0 = q[lane];
        float4 v1 = q[lane + 32];
        a0.x += v0.x * w; a0.y += v0.y * w; a0.z += v0.z * w; a0.w += v0.w * w;
        a1.x += v1.x * w; a1.y += v1.y * w; a1.z += v1.z * w; a1.w += v1.w * w;
    }

    float4 b0 = ((const float4*)bias)[lane];
    float4 b1 = ((const float4*)bias)[lane + 32];
    a0.x = fmaxf(a0.x + b0.x, 0.f); a0.y = fmaxf(a0.y + b0.y, 0.f);
    a0.z = fmaxf(a0.z + b0.z, 0.f); a0.w = fmaxf(a0.w + b0.w, 0.f);
    a1.x = fmaxf(a1.x + b1.x, 0.f); a1.y = fmaxf(a1.y + b1.y, 0.f);
    a1.z = fmaxf(a1.z + b1.z, 0.f); a1.w = fmaxf(a1.w + b1.w, 0.f);

    float4* op = (float4*)(hout + (size_t)node * HH);
    op[lane] = a0;
    op[lane + 32] = a1;
}

// ============================================================
// softmax per row, one warp per row
// ============================================================
__global__ void softmax_kernel(const float* __restrict__ in, float* __restrict__ out) {
    int warp = (blockIdx.x * blockDim.x + threadIdx.x) >> 5;
    int lane = threadIdx.x & 31;
    if (warp >= NN) return;
    const float4* ip = (const float4*)(in + (size_t)warp * DOUT);
    float4 a = ip[lane];
    float4 b = ip[lane + 32];
    float m = fmaxf(fmaxf(fmaxf(a.x, a.y), fmaxf(a.z, a.w)),
                    fmaxf(fmaxf(b.x, b.y), fmaxf(b.z, b.w)));
#pragma unroll
    for (int o = 16; o > 0; o >>= 1)
        m = fmaxf(m, __shfl_xor_sync(0xFFFFFFFFu, m, o));
    a.x = __expf(a.x - m); a.y = __expf(a.y - m); a.z = __expf(a.z - m); a.w = __expf(a.w - m);
    b.x = __expf(b.x - m); b.y = __expf(b.y - m); b.z = __expf(b.z - m); b.w = __expf(b.w - m);
    float s = a.x + a.y + a.z + a.w + b.x + b.y + b.z + b.w;
#pragma unroll
    for (int o = 16; o > 0; o >>= 1)
        s += __shfl_xor_sync(0xFFFFFFFFu, s, o);
    float inv = 1.0f / s;
    a.x *= inv; a.y *= inv; a.z *= inv; a.w *= inv;
    b.x *= inv; b.y *= inv; b.z *= inv; b.w *= inv;
    float4* op = (float4*)(out + (size_t)warp * DOUT);
    op[lane] = a;
    op[lane + 32] = b;
}

// ============================================================
// host launch
// ============================================================
extern "C" void kernel_launch(void* const* d_in, const int* in_sizes, int n_in,
                              void* d_out, int out_size)
{
    const float* x    = (const float*)d_in[0];
    const int* ei     = (const int*)d_in[1];   // int32
    const float* W1  = (const float*)d_in[2];
    const float* b1  = (const float*)d_in[3];
    const float* Wg1 = (const float*)d_in[4];
    const float* bg1 = (const float*)d_in[5];
    const float* Wg2 = (const float*)d_in[6];
    const float* bg2 = (const float*)d_in[7];
    const float* W2  = (const float*)d_in[8];
    const float* b2  = (const float*)d_in[9];
    const float* W3  = (const float*)d_in[10];
    const float* b3  = (const float*)d_in[11];
    float* out = (float*)d_out;

    int E = in_sizes[1] / 2;

    float *h, *hW, *agg;
    unsigned char *ph, *pl;
    cudaGetSymbolAddress((void**)&h, g_h);
    cudaGetSymbolAddress((void**)&hW, g_hW);
    cudaGetSymbolAddress((void**)&agg, g_agg);
    cudaGetSymbolAddress((void**)&ph, g_packh);
    cudaGetSymbolAddress((void**)&pl, g_packl);

    const int SMEMSZ = 2 * BUF;   // 64KB
    cudaFuncSetAttribute(hmma_gemm_kernel<true, true>,
                         cudaFuncAttributeMaxDynamicSharedMemorySize, SMEMSZ);
    cudaFuncSetAttribute(hmma_gemm_kernel<false, false>,
                         cudaFuncAttributeMaxDynamicSharedMemorySize, SMEMSZ);
    cudaFuncSetAttribute(hmma_gemm_kernel<true, false>,
                         cudaFuncAttributeMaxDynamicSharedMemorySize, SMEMSZ);

    dim3 gemmGrid((NN + 127) / 128, 2);
    const int NODE_WARPS = (NN * 32 + 255) / 256;

    // pack weights
    {
        dim3 pg((256 * 256 + 255) / 256, 5);
        pack_weights_kernel<<<pg, 256>>>(W1, Wg1, Wg2, W2, W3);
    }
    // degrees + dinv + scan
    zero_int_kernel<<<NBLK, 256>>>();
    deg_count_kernel<<<(E + 255) / 256, 256>>>(ei, E);
    dinv_kernel<<<NBLK, 256>>>();
    scan1_kernel<<<NBLK, 256>>>();

    // layer 1: h = relu(x @ W1 + b1)
    hmma_gemm_kernel<true, true><<<gemmGrid, 256, SMEMSZ>>>(
        x, ph + 0 * WPACK, pl + 0 * WPACK, b1, h, NN, DIN);

    // finish CSR
    scan2_kernel<<<1, 256>>>();
    scan3_kernel<<<NBLK, 256>>>();
    fill_csr_kernel<<<(E + 255) / 256, 256>>>(ei, E);

    // conv 1
    hmma_gemm_kernel<false, false><<<gemmGrid, 256, SMEMSZ>>>(
        h, ph + 1 * WPACK, pl + 1 * WPACK, nullptr, hW, NN, HH);
    gather_kernel<<<NODE_WARPS, 256>>>(hW, bg1, h);

    // conv 2
    hmma_gemm_kernel<false, false><<<gemmGrid, 256, SMEMSZ>>>(
        h, ph + 2 * WPACK, pl + 2 * WPACK, nullptr, hW, NN, HH);
    gather_kernel<<<NODE_WARPS, 256>>>(hW, bg2, h);

    // layer 4: hW = relu(h @ W2 + b2)
    hmma_gemm_kernel<true, true><<<gemmGrid, 256, SMEMSZ>>>(
        h, ph + 3 * WPACK, pl + 3 * WPACK, b2, hW, NN, HH);

    // layer 5 logits: agg = hW @ W3 + b3
    hmma_gemm_kernel<true, false><<<gemmGrid, 256, SMEMSZ>>>(
        hW, ph + 4 * WPACK, pl + 4 * WPACK, b3, agg, NN, HH);

    // softmax -> out
    softmax_kernel<<<(NN * 32 + 255) / 256, 256>>>(agg, out);
}

// round 13
// speedup vs baseline: 2.7683x; 1.0136x over previous
#include <cuda_runtime.h>
#include <cuda_bf16.h>
#include <math.h>

#define NN 50000
#define DIN 128
#define HH 256
#define DOUT 256
#define NBLK 196          // ceil(NN/256)
#define EMAXC 320000

// ---- scratch (device globals; no allocation allowed) ----
__device__ float g_h[NN * HH];
__device__ float g_hW[NN * HH];
__device__ float g_agg[NN * HH];
__device__ float g_dinv[NN];
__device__ int   g_degi[NN];
__device__ int   g_cursor[NN];
__device__ int   g_rowstart[NN];
__device__ int   g_esrc[EMAXC];
__device__ int   g_blocksum[256];

// packed weights: per weight/term: [nh 2][chunk K/32][8KB: n 128 rows x 32 bf16, swizzled]
#define WPACK 131072
__device__ __align__(16) unsigned char g_packh[5 * WPACK];
__device__ __align__(16) unsigned char g_packl[5 * WPACK];

// ============================================================
// mma.sync m16n8k16 bf16 (row.col), fp32 accum + ldmatrix + cp.async
// ============================================================
__device__ __forceinline__ void mma16816(float* c, const unsigned* a, const unsigned* b) {
    asm volatile(
        "mma.sync.aligned.m16n8k16.row.col.f32.bf16.bf16.f32 "
        "{%0,%1,%2,%3}, {%4,%5,%6,%7}, {%8,%9}, {%0,%1,%2,%3};"
        : "+f"(c[0]), "+f"(c[1]), "+f"(c[2]), "+f"(c[3])
        : "r"(a[0]), "r"(a[1]), "r"(a[2]), "r"(a[3]), "r"(b[0]), "r"(b[1]));
}
__device__ __forceinline__ void ldsm4(unsigned* r, unsigned addr) {
    asm volatile("ldmatrix.sync.aligned.m8n8.x4.shared.b16 {%0,%1,%2,%3}, [%4];"
                 : "=r"(r[0]), "=r"(r[1]), "=r"(r[2]), "=r"(r[3]) : "r"(addr));
}
__device__ __forceinline__ void cpasync16(unsigned saddr, const void* gaddr) {
    asm volatile("cp.async.cg.shared.global [%0], [%1], 16;" :: "r"(saddr), "l"(gaddr));
}
__device__ __forceinline__ void cpcommit() { asm volatile("cp.async.commit_group;"); }
__device__ __forceinline__ void cpwait0() { asm volatile("cp.async.wait_group 0;" ::: "memory"); }

__device__ __forceinline__ unsigned pack_bf2(__nv_bfloat16 x, __nv_bfloat16 y) {
    return ((unsigned)__bfloat16_as_ushort(y) << 16) | __bfloat16_as_ushort(x);
}
// swizzled byte offset within an 8KB tile: row (0..127) of 64B, granule g (0..3), byte b (0..15)
__device__ __host__ __forceinline__ int swz_off(int row, int g, int b) {
    return row * 64 + ((g ^ ((row >> 1) & 3)) << 4) + b;
}

// ============================================================
// weight prepack: W[K,256] fp32 -> hi/lo bf16 in ldmatrix-ready [n][k] swizzled tiles
// ============================================================
__global__ void pack_weights_kernel(const float* W1, const float* Wg1, const float* Wg2,
                                    const float* W2, const float* W3) {
    int wi = blockIdx.y;
    const float* W = (wi == 0) ? W1 : (wi == 1) ? Wg1 : (wi == 2) ? Wg2 : (wi == 3) ? W2 : W3;
    int K = (wi == 0) ? DIN : HH;
    int i = blockIdx.x * blockDim.x + threadIdx.x;
    if (i >= K * 256) return;
    int k = i >> 8, n = i & 255;
    float w = W[i];
    __nv_bfloat16 h = __float2bfloat16(w);
    __nv_bfloat16 l = __float2bfloat16(w - __bfloat162float(h));
    int c = k >> 5, kl = k & 31;
    int kp = kl >> 1, hl = kl & 1;
    int nh = n >> 7, nl = n & 127;
    size_t off = (size_t)wi * WPACK + ((size_t)(nh * (K >> 5) + c)) * 8192
               + swz_off(nl, kp >> 2, (kp & 3) * 4 + hl * 2);
    *(__nv_bfloat16*)(g_packh + off) = h;
    *(__nv_bfloat16*)(g_packl + off) = l;
}

// ============================================================
// HMMA GEMM: one CTA computes 128 rows x ALL 256 cols.
// A (hi/lo) staged in full (chunks x 16KB), B streamed per column-half with
// cp.async double buffering. 8 warps (2M x 4N), warp m64n32, BK=32.
// smem layout: A: [c](Ah 8KB | Al 8KB) at 0..chunks*16KB; B: 2 bufs x 16KB after.
// ============================================================
template <bool BIAS, bool RELU>
__global__ __launch_bounds__(256, 1) void hmma_gemm_kernel(
    const float* __restrict__ A, const unsigned char* __restrict__ Bhp,
    const unsigned char* __restrict__ Blp, const float* __restrict__ bias,
    float* __restrict__ C, int M, int K)
{
    extern __shared__ __align__(16) unsigned char smem[];
    unsigned sbase = (unsigned)__cvta_generic_to_shared(smem);

    int tid = threadIdx.x;
    int lane = tid & 31;
    int wid = tid >> 5;
    int wm = wid & 1;
    int wn = wid >> 1;
    int row0 = blockIdx.x * 128;
    int chunks = K >> 5;
    unsigned bbase = (unsigned)(chunks * 16384);   // B region offset

    // A staging geometry (per thread, 8 slots per chunk)
    int skp = tid & 15;
    int srow = tid >> 4;
    int sAoff[8];
    bool sOK[8];
#pragma unroll
    for (int it = 0; it < 8; it++) {
        int r = srow + it * 16;
        sAoff[it] = swz_off(r, skp >> 2, (skp & 3) * 4);
        sOK[it] = (row0 + r) < M;
    }

    // B cp.async geometry: 2 x 16B per term per thread
    unsigned bso0 = tid * 16, bso1 = (tid + 256) * 16;

    // ldmatrix offsets (j=0; j=1 differs by ^32)
    unsigned offA[4], offB[2];
    {
        int rA = wm * 64 + (lane & 15);
        int gA = lane >> 4;
#pragma unroll
        for (int mt = 0; mt < 4; mt++) offA[mt] = swz_off(rA + mt * 16, gA, 0);
        int nB = wn * 32 + ((lane >> 4) << 3) + (lane & 7);
        int gB = (lane >> 3) & 1;
#pragma unroll
        for (int np = 0; np < 2; np++) offB[np] = swz_off(nB + np * 16, gB, 0);
    }

    // ---- kick off first B copy, then stage ALL of A (overlaps the copy) ----
    cpasync16(sbase + bbase + bso0, Bhp + bso0);
    cpasync16(sbase + bbase + bso1, Bhp + bso1);
    cpasync16(sbase + bbase + 8192 + bso0, Blp + bso0);
    cpasync16(sbase + bbase + 8192 + bso1, Blp + bso1);
    cpcommit();

    for (int c = 0; c < chunks; c++) {
        unsigned abase = c * 16384;
#pragma unroll
        for (int it = 0; it < 8; it++) {
            int r = srow + it * 16;
            float2 v = make_float2(0.f, 0.f);
            if (sOK[it]) v = *(const float2*)&A[(size_t)(row0 + r) * K + c * 32 + skp * 2];
            __nv_bfloat16 h0 = __float2bfloat16(v.x), h1 = __float2bfloat16(v.y);
            __nv_bfloat16 l0 = __float2bfloat16(v.x - __bfloat162float(h0));
            __nv_bfloat16 l1 = __float2bfloat16(v.y - __bfloat162float(h1));
            *(unsigned*)(smem + abase + sAoff[it]) = pack_bf2(h0, h1);
            *(unsigned*)(smem + abase + 8192 + sAoff[it]) = pack_bf2(l0, l1);
        }
    }

    float acc[4][4][4];
#pragma unroll
    for (int mt = 0; mt < 4; mt++)
#pragma unroll
        for (int nt = 0; nt < 4; nt++)
#pragma unroll
            for (int q = 0; q < 4; q++) acc[mt][nt][q] = 0.0f;

    int total = 2 * chunks;
    for (int t = 0; t < total; t++) {
        int nh = (t >= chunks) ? 1 : 0;
        int c = t - nh * chunks;
        unsigned cbuf = bbase + (unsigned)((t & 1) * 16384);
        unsigned nbuf = bbase + (unsigned)(((t + 1) & 1) * 16384);
        bool more = (t + 1) < total;

        cpwait0();
        __syncthreads();

        if (more) {
            const unsigned char* bh = Bhp + (size_t)(t + 1) * 8192;
            const unsigned char* bl = Blp + (size_t)(t + 1) * 8192;
            cpasync16(sbase + nbuf + bso0, bh + bso0);
            cpasync16(sbase + nbuf + bso1, bh + bso1);
            cpasync16(sbase + nbuf + 8192 + bso0, bl + bso0);
            cpasync16(sbase + nbuf + 8192 + bso1, bl + bso1);
            cpcommit();
        }

        unsigned abase = c * 16384;
#pragma unroll
        for (int j = 0; j < 2; j++) {
            unsigned jx = j ? 32u : 0u;
            unsigned bfh[2][4], bfl[2][4];
#pragma unroll
            for (int np = 0; np < 2; np++) {
                ldsm4(bfh[np], sbase + cbuf + (offB[np] ^ jx));
                ldsm4(bfl[np], sbase + cbuf + 8192 + (offB[np] ^ jx));
            }
            unsigned afh[4][4], afl[4][4];
#pragma unroll
            for (int mt = 0; mt < 4; mt++) {
                ldsm4(afh[mt], sbase + abase + (offA[mt] ^ jx));
                ldsm4(afl[mt], sbase + abase + 8192 + (offA[mt] ^ jx));
            }
#pragma unroll
            for (int mt = 0; mt < 4; mt++)
#pragma unroll
                for (int nt = 0; nt < 4; nt++) {
                    const unsigned* bh = &bfh[nt >> 1][(nt & 1) * 2];
                    const unsigned* bl = &bfl[nt >> 1][(nt & 1) * 2];
                    mma16816(acc[mt][nt], afh[mt], bh);
                    mma16816(acc[mt][nt], afh[mt], bl);
                    mma16816(acc[mt][nt], afl[mt], bh);
                }
        }

        // end of a column half: write out + reset accumulators
        if (c == chunks - 1) {
            int colBlock = nh * 128;
#pragma unroll
            for (int mt = 0; mt < 4; mt++) {
                int r0 = row0 + wm * 64 + mt * 16 + (lane >> 2);
#pragma unroll
                for (int nt = 0; nt < 4; nt++) {
                    int col = colBlock + wn * 32 + nt * 8 + (lane & 3) * 2;
                    float b0 = 0.f, b1 = 0.f;
                    if (BIAS) { b0 = bias[col]; b1 = bias[col + 1]; }
#pragma unroll
                    for (int hh = 0; hh < 2; hh++) {
                        int r = r0 + hh * 8;
                        if (r >= M) continue;
                        float v0 = acc[mt][nt][hh * 2 + 0];
                        float v1 = acc[mt][nt][hh * 2 + 1];
                        if (BIAS) { v0 += b0; v1 += b1; }
                        if (RELU) { v0 = fmaxf(v0, 0.f); v1 = fmaxf(v1, 0.f); }
                        *(float2*)&C[(size_t)r * 256 + col] = make_float2(v0, v1);
                    }
#pragma unroll
                    for (int q = 0; q < 4; q++) acc[mt][nt][q] = 0.0f;
                }
            }
        }
    }
}

// ============================================================
// CSR build (edge_index INT32: src = ei[e], dst = ei[E+e])
// ============================================================
__global__ void zero_int_kernel() {
    int i = blockIdx.x * blockDim.x + threadIdx.x;
    if (i < NN) { g_degi[i] = 0; g_cursor[i] = 0; }
}
__global__ void deg_count_kernel(const int* __restrict__ ei, int E) {
    int e = blockIdx.x * blockDim.x + threadIdx.x;
    if (e < E) {
        int d = ei[E + e];
        if ((unsigned)d < (unsigned)NN) atomicAdd(&g_degi[d], 1);
    }
}
__global__ void dinv_kernel() {
    int i = blockIdx.x * blockDim.x + threadIdx.x;
    if (i < NN) g_dinv[i] = rsqrtf((float)g_degi[i] + 1.0f);
}
__global__ void scan1_kernel() {
    __shared__ int sh[256];
    int t = threadIdx.x;
    int i = blockIdx.x * 256 + t;
    int v = (i < NN) ? g_degi[i] : 0;
    sh[t] = v;
    __syncthreads();
#pragma unroll
    for (int off = 1; off < 256; off <<= 1) {
        int x = (t >= off) ? sh[t - off] : 0;
        __syncthreads();
        sh[t] += x;
        __syncthreads();
    }
    if (i < NN) g_rowstart[i] = sh[t] - v;
    if (t == 255) g_blocksum[blockIdx.x] = sh[255];
}
__global__ void scan2_kernel() {
    __shared__ int sh[256];
    int t = threadIdx.x;
    int v = (t < NBLK) ? g_blocksum[t] : 0;
    sh[t] = v;
    __syncthreads();
#pragma unroll
    for (int off = 1; off < 256; off <<= 1) {
        int x = (t >= off) ? sh[t - off] : 0;
        __syncthreads();
        sh[t] += x;
        __syncthreads();
    }
    if (t < NBLK) g_blocksum[t] = sh[t] - v;
}
__global__ void scan3_kernel() {
    int i = blockIdx.x * blockDim.x + threadIdx.x;
    if (i < NN) g_rowstart[i] += g_blocksum[i >> 8];
}
__global__ void fill_csr_kernel(const int* __restrict__ ei, int E) {
    int e = blockIdx.x * blockDim.x + threadIdx.x;
    if (e >= E) return;
    int s = ei[e];
    int d = ei[E + e];
    if ((unsigned)s >= (unsigned)NN || (unsigned)d >= (unsigned)NN) return;
    int pos = g_rowstart[d] + atomicAdd(&g_cursor[d], 1);
    if (pos < EMAXC) g_esrc[pos] = s;
}

// ============================================================
// fused gather: h[d] = relu( sum hW[s]*dinv[s]*dinv[d] + hW[d]*dinv[d]^2 + bias )
// ============================================================
__global__ void gather_kernel(const float* __restrict__ hW,
                              const float* __restrict__ bias,
                              float* __restrict__ hout)
{
    int node = (blockIdx.x * blockDim.x + threadIdx.x) >> 5;
    int lane = threadIdx.x & 31;
    if (node >= NN) return;
    float dv = g_dinv[node];
    int base = g_rowstart[node];
    int cnt = g_degi[node];

    const float4* sp = (const float4*)(hW + (size_t)node * HH);
    float4 a0 = sp[lane];
    float4 a1 = sp[lane + 32];
    float ss = dv * dv;
    a0.x *= ss; a0.y *= ss; a0.z *= ss; a0.w *= ss;
    a1.x *= ss; a1.y *= ss; a1.z *= ss; a1.w *= ss;

#pragma unroll 2
    for (int j = 0; j < cnt; j++) {
        int s = g_esrc[base + j];
        float w = g_dinv[s] * dv;
        const float4* q = (const float4*)(hW + (size_t)s * HH);
        float4 v0 = q[lane];
        float4 v1 = q[lane + 32];
        a0.x += v0.x * w; a0.y += v0.y * w; a0.z += v0.z * w; a0.w += v0.w * w;
        a1.x += v1.x * w; a1.y += v1.y * w; a1.z += v1.z * w; a1.w += v1.w * w;
    }

    float4 b0 = ((const float4*)bias)[lane];
    float4 b1 = ((const float4*)bias)[lane + 32];
    a0.x = fmaxf(a0.x + b0.x, 0.f); a0.y = fmaxf(a0.y + b0.y, 0.f);
    a0.z = fmaxf(a0.z + b0.z, 0.f); a0.w = fmaxf(a0.w + b0.w, 0.f);
    a1.x = fmaxf(a1.x + b1.x, 0.f); a1.y = fmaxf(a1.y + b1.y, 0.f);
    a1.z = fmaxf(a1.z + b1.z, 0.f); a1.w = fmaxf(a1.w + b1.w, 0.f);

    float4* op = (float4*)(hout + (size_t)node * HH);
    op[lane] = a0;
    op[lane + 32] = a1;
}

// ============================================================
// softmax per row, one warp per row
// ============================================================
__global__ void softmax_kernel(const float* __restrict__ in, float* __restrict__ out) {
    int warp = (blockIdx.x * blockDim.x + threadIdx.x) >> 5;
    int lane = threadIdx.x & 31;
    if (warp >= NN) return;
    const float4* ip = (const float4*)(in + (size_t)warp * DOUT);
    float4 a = ip[lane];
    float4 b = ip[lane + 32];
    float m = fmaxf(fmaxf(fmaxf(a.x, a.y), fmaxf(a.z, a.w)),
                    fmaxf(fmaxf(b.x, b.y), fmaxf(b.z, b.w)));
#pragma unroll
    for (int o = 16; o > 0; o >>= 1)
        m = fmaxf(m, __shfl_xor_sync(0xFFFFFFFFu, m, o));
    a.x = __expf(a.x - m); a.y = __expf(a.y - m); a.z = __expf(a.z - m); a.w = __expf(a.w - m);
    b.x = __expf(b.x - m); b.y = __expf(b.y - m); b.z = __expf(b.z - m); b.w = __expf(b.w - m);
    float s = a.x + a.y + a.z + a.w + b.x + b.y + b.z + b.w;
#pragma unroll
    for (int o = 16; o > 0; o >>= 1)
        s += __shfl_xor_sync(0xFFFFFFFFu, s, o);
    float inv = 1.0f / s;
    a.x *= inv; a.y *= inv; a.z *= inv; a.w *= inv;
    b.x *= inv; b.y *= inv; b.z *= inv; b.w *= inv;
    float4* op = (float4*)(out + (size_t)warp * DOUT);
    op[lane] = a;
    op[lane + 32] = b;
}

// ============================================================
// host launch
// ============================================================
extern "C" void kernel_launch(void* const* d_in, const int* in_sizes, int n_in,
                              void* d_out, int out_size)
{
    const float* x    = (const float*)d_in[0];
    const int* ei     = (const int*)d_in[1];   // int32
    const float* W1  = (const float*)d_in[2];
    const float* b1  = (const float*)d_in[3];
    const float* Wg1 = (const float*)d_in[4];
    const float* bg1 = (const float*)d_in[5];
    const float* Wg2 = (const float*)d_in[6];
    const float* bg2 = (const float*)d_in[7];
    const float* W2  = (const float*)d_in[8];
    const float* b2  = (const float*)d_in[9];
    const float* W3  = (const float*)d_in[10];
    const float* b3  = (const float*)d_in[11];
    float* out = (float*)d_out;

    int E = in_sizes[1] / 2;

    float *h, *hW, *agg;
    unsigned char *ph, *pl;
    cudaGetSymbolAddress((void**)&h, g_h);
    cudaGetSymbolAddress((void**)&hW, g_hW);
    cudaGetSymbolAddress((void**)&agg, g_agg);
    cudaGetSymbolAddress((void**)&ph, g_packh);
    cudaGetSymbolAddress((void**)&pl, g_packl);

    const int SM128 = 4 * 16384 + 32768;   // K=128: 96KB
    const int SM256 = 8 * 16384 + 32768;   // K=256: 160KB
    cudaFuncSetAttribute(hmma_gemm_kernel<true, true>,
                         cudaFuncAttributeMaxDynamicSharedMemorySize, SM256);
    cudaFuncSetAttribute(hmma_gemm_kernel<false, false>,
                         cudaFuncAttributeMaxDynamicSharedMemorySize, SM256);
    cudaFuncSetAttribute(hmma_gemm_kernel<true, false>,
                         cudaFuncAttributeMaxDynamicSharedMemorySize, SM256);

    const int GEMM_GRID = (NN + 127) / 128;
    const int NODE_WARPS = (NN * 32 + 255) / 256;

    // pack weights
    {
        dim3 pg((256 * 256 + 255) / 256, 5);
        pack_weights_kernel<<<pg, 256>>>(W1, Wg1, Wg2, W2, W3);
    }
    // degrees + dinv + scan
    zero_int_kernel<<<NBLK, 256>>>();
    deg_count_kernel<<<(E + 255) / 256, 256>>>(ei, E);
    dinv_kernel<<<NBLK, 256>>>();
    scan1_kernel<<<NBLK, 256>>>();

    // layer 1: h = relu(x @ W1 + b1)
    hmma_gemm_kernel<true, true><<<GEMM_GRID, 256, SM128>>>(
        x, ph + 0 * WPACK, pl + 0 * WPACK, b1, h, NN, DIN);

    // finish CSR
    scan2_kernel<<<1, 256>>>();
    scan3_kernel<<<NBLK, 256>>>();
    fill_csr_kernel<<<(E + 255) / 256, 256>>>(ei, E);

    // conv 1
    hmma_gemm_kernel<false, false><<<GEMM_GRID, 256, SM256>>>(
        h, ph + 1 * WPACK, pl + 1 * WPACK, nullptr, hW, NN, HH);
    gather_kernel<<<NODE_WARPS, 256>>>(hW, bg1, h);

    // conv 2
    hmma_gemm_kernel<false, false><<<GEMM_GRID, 256, SM256>>>(
        h, ph + 2 * WPACK, pl + 2 * WPACK, nullptr, hW, NN, HH);
    gather_kernel<<<NODE_WARPS, 256>>>(hW, bg2, h);

    // layer 4: hW = relu(h @ W2 + b2)
    hmma_gemm_kernel<true, true><<<GEMM_GRID, 256, SM256>>>(
        h, ph + 3 * WPACK, pl + 3 * WPACK, b2, hW, NN, HH);

    // layer 5 logits: agg = hW @ W3 + b3
    hmma_gemm_kernel<true, false><<<GEMM_GRID, 256, SM256>>>(
        hW, ph + 4 * WPACK, pl + 4 * WPACK, b3, agg, NN, HH);

    // softmax -> out
    softmax_kernel<<<(NN * 32 + 255) / 256, 256>>>(agg, out);
}

// round 14
// speedup vs baseline: 2.8283x; 1.0217x over previous
#include <cuda_runtime.h>
#include <cuda_bf16.h>
#include <math.h>

#define NN 50000
#define DIN 128
#define HH 256
#define DOUT 256
#define NBLK 196          // ceil(NN/256)
#define EMAXC 320000

// ---- scratch (device globals; no allocation allowed) ----
__device__ float g_h[NN * HH];
__device__ float g_hW[NN * HH];
__device__ float g_agg[NN * HH];
__device__ float g_dinv[NN];
__device__ int   g_degi[NN];
__device__ int   g_cursor[NN];
__device__ int   g_rowstart[NN];
__device__ int   g_esrc[EMAXC];
__device__ int   g_blocksum[256];

// packed weights: per weight/term: [nh 2][chunk K/32][8KB: n 128 rows x 32 bf16, swizzled]
#define WPACK 131072
__device__ __align__(16) unsigned char g_packh[5 * WPACK];
__device__ __align__(16) unsigned char g_packl[5 * WPACK];

// ============================================================
// mma.sync m16n8k16 bf16 (row.col), fp32 accum + ldmatrix + cp.async
// ============================================================
__device__ __forceinline__ void mma16816(float* c, const unsigned* a, const unsigned* b) {
    asm volatile(
        "mma.sync.aligned.m16n8k16.row.col.f32.bf16.bf16.f32 "
        "{%0,%1,%2,%3}, {%4,%5,%6,%7}, {%8,%9}, {%0,%1,%2,%3};"
        : "+f"(c[0]), "+f"(c[1]), "+f"(c[2]), "+f"(c[3])
        : "r"(a[0]), "r"(a[1]), "r"(a[2]), "r"(a[3]), "r"(b[0]), "r"(b[1]));
}
__device__ __forceinline__ void ldsm4(unsigned* r, unsigned addr) {
    asm volatile("ldmatrix.sync.aligned.m8n8.x4.shared.b16 {%0,%1,%2,%3}, [%4];"
                 : "=r"(r[0]), "=r"(r[1]), "=r"(r[2]), "=r"(r[3]) : "r"(addr));
}
__device__ __forceinline__ void cpasync16(unsigned saddr, const void* gaddr) {
    asm volatile("cp.async.cg.shared.global [%0], [%1], 16;" :: "r"(saddr), "l"(gaddr));
}
__device__ __forceinline__ void cpcommit() { asm volatile("cp.async.commit_group;"); }
__device__ __forceinline__ void cpwait0() { asm volatile("cp.async.wait_group 0;" ::: "memory"); }

__device__ __forceinline__ unsigned pack_bf2(__nv_bfloat16 x, __nv_bfloat16 y) {
    return ((unsigned)__bfloat16_as_ushort(y) << 16) | __bfloat16_as_ushort(x);
}
// swizzled byte offset within an 8KB tile: row (0..127) of 64B, granule g (0..3), byte b (0..15)
__device__ __host__ __forceinline__ int swz_off(int row, int g, int b) {
    return row * 64 + ((g ^ ((row >> 1) & 3)) << 4) + b;
}

// ============================================================
// weight prepack: W[K,256] fp32 -> hi/lo bf16 in ldmatrix-ready [n][k] swizzled tiles
// ============================================================
__global__ void pack_weights_kernel(const float* W1, const float* Wg1, const float* Wg2,
                                    const float* W2, const float* W3) {
    int wi = blockIdx.y;
    const float* W = (wi == 0) ? W1 : (wi == 1) ? Wg1 : (wi == 2) ? Wg2 : (wi == 3) ? W2 : W3;
    int K = (wi == 0) ? DIN : HH;
    int i = blockIdx.x * blockDim.x + threadIdx.x;
    if (i >= K * 256) return;
    int k = i >> 8, n = i & 255;
    float w = W[i];
    __nv_bfloat16 h = __float2bfloat16(w);
    __nv_bfloat16 l = __float2bfloat16(w - __bfloat162float(h));
    int c = k >> 5, kl = k & 31;
    int kp = kl >> 1, hl = kl & 1;
    int nh = n >> 7, nl = n & 127;
    size_t off = (size_t)wi * WPACK + ((size_t)(nh * (K >> 5) + c)) * 8192
               + swz_off(nl, kp >> 2, (kp & 3) * 4 + hl * 2);
    *(__nv_bfloat16*)(g_packh + off) = h;
    *(__nv_bfloat16*)(g_packl + off) = l;
}

// ============================================================
// HMMA GEMM: one CTA computes 128 rows x ALL 256 cols.
// A (hi/lo) staged in full (chunks x 16KB), B streamed per column-half with
// cp.async double buffering. 8 warps (2M x 4N), warp m64n32, BK=32.
// ============================================================
template <bool BIAS, bool RELU>
__global__ __launch_bounds__(256, 1) void hmma_gemm_kernel(
    const float* __restrict__ A, const unsigned char* __restrict__ Bhp,
    const unsigned char* __restrict__ Blp, const float* __restrict__ bias,
    float* __restrict__ C, int M, int K)
{
    extern __shared__ __align__(16) unsigned char smem[];
    unsigned sbase = (unsigned)__cvta_generic_to_shared(smem);

    int tid = threadIdx.x;
    int lane = tid & 31;
    int wid = tid >> 5;
    int wm = wid & 1;
    int wn = wid >> 1;
    int row0 = blockIdx.x * 128;
    int chunks = K >> 5;
    unsigned bbase = (unsigned)(chunks * 16384);

    int skp = tid & 15;
    int srow = tid >> 4;
    int sAoff[8];
    bool sOK[8];
#pragma unroll
    for (int it = 0; it < 8; it++) {
        int r = srow + it * 16;
        sAoff[it] = swz_off(r, skp >> 2, (skp & 3) * 4);
        sOK[it] = (row0 + r) < M;
    }

    unsigned bso0 = tid * 16, bso1 = (tid + 256) * 16;

    unsigned offA[4], offB[2];
    {
        int rA = wm * 64 + (lane & 15);
        int gA = lane >> 4;
#pragma unroll
        for (int mt = 0; mt < 4; mt++) offA[mt] = swz_off(rA + mt * 16, gA, 0);
        int nB = wn * 32 + ((lane >> 4) << 3) + (lane & 7);
        int gB = (lane >> 3) & 1;
#pragma unroll
        for (int np = 0; np < 2; np++) offB[np] = swz_off(nB + np * 16, gB, 0);
    }

    // kick off first B copy, then stage ALL of A (overlaps the copy)
    cpasync16(sbase + bbase + bso0, Bhp + bso0);
    cpasync16(sbase + bbase + bso1, Bhp + bso1);
    cpasync16(sbase + bbase + 8192 + bso0, Blp + bso0);
    cpasync16(sbase + bbase + 8192 + bso1, Blp + bso1);
    cpcommit();

    for (int c = 0; c < chunks; c++) {
        unsigned abase = c * 16384;
#pragma unroll
        for (int it = 0; it < 8; it++) {
            int r = srow + it * 16;
            float2 v = make_float2(0.f, 0.f);
            if (sOK[it]) v = *(const float2*)&A[(size_t)(row0 + r) * K + c * 32 + skp * 2];
            __nv_bfloat16 h0 = __float2bfloat16(v.x), h1 = __float2bfloat16(v.y);
            __nv_bfloat16 l0 = __float2bfloat16(v.x - __bfloat162float(h0));
            __nv_bfloat16 l1 = __float2bfloat16(v.y - __bfloat162float(h1));
            *(unsigned*)(smem + abase + sAoff[it]) = pack_bf2(h0, h1);
            *(unsigned*)(smem + abase + 8192 + sAoff[it]) = pack_bf2(l0, l1);
        }
    }

    float acc[4][4][4];
#pragma unroll
    for (int mt = 0; mt < 4; mt++)
#pragma unroll
        for (int nt = 0; nt < 4; nt++)
#pragma unroll
            for (int q = 0; q < 4; q++) acc[mt][nt][q] = 0.0f;

    int total = 2 * chunks;
    for (int t = 0; t < total; t++) {
        int nh = (t >= chunks) ? 1 : 0;
        int c = t - nh * chunks;
        unsigned cbuf = bbase + (unsigned)((t & 1) * 16384);
        unsigned nbuf = bbase + (unsigned)(((t + 1) & 1) * 16384);
        bool more = (t + 1) < total;

        cpwait0();
        __syncthreads();

        if (more) {
            const unsigned char* bh = Bhp + (size_t)(t + 1) * 8192;
            const unsigned char* bl = Blp + (size_t)(t + 1) * 8192;
            cpasync16(sbase + nbuf + bso0, bh + bso0);
            cpasync16(sbase + nbuf + bso1, bh + bso1);
            cpasync16(sbase + nbuf + 8192 + bso0, bl + bso0);
            cpasync16(sbase + nbuf + 8192 + bso1, bl + bso1);
            cpcommit();
        }

        unsigned abase = c * 16384;
#pragma unroll
        for (int j = 0; j < 2; j++) {
            unsigned jx = j ? 32u : 0u;
            unsigned bfh[2][4], bfl[2][4];
#pragma unroll
            for (int np = 0; np < 2; np++) {
                ldsm4(bfh[np], sbase + cbuf + (offB[np] ^ jx));
                ldsm4(bfl[np], sbase + cbuf + 8192 + (offB[np] ^ jx));
            }
            unsigned afh[4][4], afl[4][4];
#pragma unroll
            for (int mt = 0; mt < 4; mt++) {
                ldsm4(afh[mt], sbase + abase + (offA[mt] ^ jx));
                ldsm4(afl[mt], sbase + abase + 8192 + (offA[mt] ^ jx));
            }
#pragma unroll
            for (int mt = 0; mt < 4; mt++)
#pragma unroll
                for (int nt = 0; nt < 4; nt++) {
                    const unsigned* bh = &bfh[nt >> 1][(nt & 1) * 2];
                    const unsigned* bl = &bfl[nt >> 1][(nt & 1) * 2];
                    mma16816(acc[mt][nt], afh[mt], bh);
                    mma16816(acc[mt][nt], afh[mt], bl);
                    mma16816(acc[mt][nt], afl[mt], bh);
                }
        }

        if (c == chunks - 1) {
            int colBlock = nh * 128;
#pragma unroll
            for (int mt = 0; mt < 4; mt++) {
                int r0 = row0 + wm * 64 + mt * 16 + (lane >> 2);
#pragma unroll
                for (int nt = 0; nt < 4; nt++) {
                    int col = colBlock + wn * 32 + nt * 8 + (lane & 3) * 2;
                    float b0 = 0.f, b1 = 0.f;
                    if (BIAS) { b0 = bias[col]; b1 = bias[col + 1]; }
#pragma unroll
                    for (int hh = 0; hh < 2; hh++) {
                        int r = r0 + hh * 8;
                        if (r >= M) continue;
                        float v0 = acc[mt][nt][hh * 2 + 0];
                        float v1 = acc[mt][nt][hh * 2 + 1];
                        if (BIAS) { v0 += b0; v1 += b1; }
                        if (RELU) { v0 = fmaxf(v0, 0.f); v1 = fmaxf(v1, 0.f); }
                        *(float2*)&C[(size_t)r * 256 + col] = make_float2(v0, v1);
                    }
#pragma unroll
                    for (int q = 0; q < 4; q++) acc[mt][nt][q] = 0.0f;
                }
            }
        }
    }
}

// ============================================================
// CSR build (edge_index INT32: src = ei[e], dst = ei[E+e])
// ============================================================
__global__ void zero_int_kernel() {
    int i = blockIdx.x * blockDim.x + threadIdx.x;
    if (i < NN) { g_degi[i] = 0; g_cursor[i] = 0; }
}
__global__ void deg_count_kernel(const int* __restrict__ ei, int E) {
    int e = blockIdx.x * blockDim.x + threadIdx.x;
    if (e < E) {
        int d = ei[E + e];
        if ((unsigned)d < (unsigned)NN) atomicAdd(&g_degi[d], 1);
    }
}
__global__ void dinv_kernel() {
    int i = blockIdx.x * blockDim.x + threadIdx.x;
    if (i < NN) g_dinv[i] = rsqrtf((float)g_degi[i] + 1.0f);
}
__global__ void scan1_kernel() {
    __shared__ int sh[256];
    int t = threadIdx.x;
    int i = blockIdx.x * 256 + t;
    int v = (i < NN) ? g_degi[i] : 0;
    sh[t] = v;
    __syncthreads();
#pragma unroll
    for (int off = 1; off < 256; off <<= 1) {
        int x = (t >= off) ? sh[t - off] : 0;
        __syncthreads();
        sh[t] += x;
        __syncthreads();
    }
    if (i < NN) g_rowstart[i] = sh[t] - v;
    if (t == 255) g_blocksum[blockIdx.x] = sh[255];
}
__global__ void scan2_kernel() {
    __shared__ int sh[256];
    int t = threadIdx.x;
    int v = (t < NBLK) ? g_blocksum[t] : 0;
    sh[t] = v;
    __syncthreads();
#pragma unroll
    for (int off = 1; off < 256; off <<= 1) {
        int x = (t >= off) ? sh[t - off] : 0;
        __syncthreads();
        sh[t] += x;
        __syncthreads();
    }
    if (t < NBLK) g_blocksum[t] = sh[t] - v;
}
__global__ void scan3_kernel() {
    int i = blockIdx.x * blockDim.x + threadIdx.x;
    if (i < NN) g_rowstart[i] += g_blocksum[i >> 8];
}
__global__ void fill_csr_kernel(const int* __restrict__ ei, int E) {
    int e = blockIdx.x * blockDim.x + threadIdx.x;
    if (e >= E) return;
    int s = ei[e];
    int d = ei[E + e];
    if ((unsigned)s >= (unsigned)NN || (unsigned)d >= (unsigned)NN) return;
    int pos = g_rowstart[d] + atomicAdd(&g_cursor[d], 1);
    if (pos < EMAXC) g_esrc[pos] = s;
}

// ============================================================
// fused gather: h[d] = relu( sum hW[s]*dinv[s]*dinv[d] + hW[d]*dinv[d]^2 + bias )
// ============================================================
__global__ void gather_kernel(const float* __restrict__ hW,
                              const float* __restrict__ bias,
                              float* __restrict__ hout)
{
    int node = (blockIdx.x * blockDim.x + threadIdx.x) >> 5;
    int lane = threadIdx.x & 31;
    if (node >= NN) return;
    float dv = g_dinv[node];
    int base = g_rowstart[node];
    int cnt = g_degi[node];

    const float4* sp = (const float4*)(hW + (size_t)node * HH);
    float4 a0 = sp[lane];
    float4 a1 = sp[lane + 32];
    float ss = dv * dv;
    a0.x *= ss; a0.y *= ss; a0.z *= ss; a0.w *= ss;
    a1.x *= ss; a1.y *= ss; a1.z *= ss; a1.w *= ss;

#pragma unroll 2
    for (int j = 0; j < cnt; j++) {
        int s = g_esrc[base + j];
        float w = g_dinv[s] * dv;
        const float4* q = (const float4*)(hW + (size_t)s * HH);
        float4 v0 = q[lane];
        float4 v1 = q[lane + 32];
        a0.x += v0.x * w; a0.y += v0.y * w; a0.z += v0.z * w; a0.w += v0.w * w;
        a1.x += v1.x * w; a1.y += v1.y * w; a1.z += v1.z * w; a1.w += v1.w * w;
    }

    float4 b0 = ((const float4*)bias)[lane];
    float4 b1 = ((const float4*)bias)[lane + 32];
    a0.x = fmaxf(a0.x + b0.x, 0.f); a0.y = fmaxf(a0.y + b0.y, 0.f);
    a0.z = fmaxf(a0.z + b0.z, 0.f); a0.w = fmaxf(a0.w + b0.w, 0.f);
    a1.x = fmaxf(a1.x + b1.x, 0.f); a1.y = fmaxf(a1.y + b1.y, 0.f);
    a1.z = fmaxf(a1.z + b1.z, 0.f); a1.w = fmaxf(a1.w + b1.w, 0.f);

    float4* op = (float4*)(hout + (size_t)node * HH);
    op[lane] = a0;
    op[lane + 32] = a1;
}

// ============================================================
// softmax per row, one warp per row
// ============================================================
__global__ void softmax_kernel(const float* __restrict__ in, float* __restrict__ out) {
    int warp = (blockIdx.x * blockDim.x + threadIdx.x) >> 5;
    int lane = threadIdx.x & 31;
    if (warp >= NN) return;
    const float4* ip = (const float4*)(in + (size_t)warp * DOUT);
    float4 a = ip[lane];
    float4 b = ip[lane + 32];
    float m = fmaxf(fmaxf(fmaxf(a.x, a.y), fmaxf(a.z, a.w)),
                    fmaxf(fmaxf(b.x, b.y), fmaxf(b.z, b.w)));
#pragma unroll
    for (int o = 16; o > 0; o >>= 1)
        m = fmaxf(m, __shfl_xor_sync(0xFFFFFFFFu, m, o));
    a.x = __expf(a.x - m); a.y = __expf(a.y - m); a.z = __expf(a.z - m); a.w = __expf(a.w - m);
    b.x = __expf(b.x - m); b.y = __expf(b.y - m); b.z = __expf(b.z - m); b.w = __expf(b.w - m);
    float s = a.x + a.y + a.z + a.w + b.x + b.y + b.z + b.w;
#pragma unroll
    for (int o = 16; o > 0; o >>= 1)
        s += __shfl_xor_sync(0xFFFFFFFFu, s, o);
    float inv = 1.0f / s;
    a.x *= inv; a.y *= inv; a.z *= inv; a.w *= inv;
    b.x *= inv; b.y *= inv; b.z *= inv; b.w *= inv;
    float4* op = (float4*)(out + (size_t)warp * DOUT);
    op[lane] = a;
    op[lane + 32] = b;
}

// ============================================================
// host launch — fork CSR chain onto a side stream, join before gather-1
// ============================================================
extern "C" void kernel_launch(void* const* d_in, const int* in_sizes, int n_in,
                              void* d_out, int out_size)
{
    const float* x    = (const float*)d_in[0];
    const int* ei     = (const int*)d_in[1];   // int32
    const float* W1  = (const float*)d_in[2];
    const float* b1  = (const float*)d_in[3];
    const float* Wg1 = (const float*)d_in[4];
    const float* bg1 = (const float*)d_in[5];
    const float* Wg2 = (const float*)d_in[6];
    const float* bg2 = (const float*)d_in[7];
    const float* W2  = (const float*)d_in[8];
    const float* b2  = (const float*)d_in[9];
    const float* W3  = (const float*)d_in[10];
    const float* b3  = (const float*)d_in[11];
    float* out = (float*)d_out;

    int E = in_sizes[1] / 2;

    float *h, *hW, *agg;
    unsigned char *ph, *pl;
    cudaGetSymbolAddress((void**)&h, g_h);
    cudaGetSymbolAddress((void**)&hW, g_hW);
    cudaGetSymbolAddress((void**)&agg, g_agg);
    cudaGetSymbolAddress((void**)&ph, g_packh);
    cudaGetSymbolAddress((void**)&pl, g_packl);

    const int SM128 = 4 * 16384 + 32768;   // K=128: 96KB
    const int SM256 = 8 * 16384 + 32768;   // K=256: 160KB
    cudaFuncSetAttribute(hmma_gemm_kernel<true, true>,
                         cudaFuncAttributeMaxDynamicSharedMemorySize, SM256);
    cudaFuncSetAttribute(hmma_gemm_kernel<false, false>,
                         cudaFuncAttributeMaxDynamicSharedMemorySize, SM256);
    cudaFuncSetAttribute(hmma_gemm_kernel<true, false>,
                         cudaFuncAttributeMaxDynamicSharedMemorySize, SM256);

    const int GEMM_GRID = (NN + 127) / 128;
    const int NODE_WARPS = (NN * 32 + 255) / 256;

    // side stream + events (created per call; not destroyed mid-capture —
    // host-object only, no device allocation; graph replays never re-run this)
    cudaStream_t s2;
    cudaEvent_t evF, evJ;
    cudaStreamCreateWithFlags(&s2, cudaStreamNonBlocking);
    cudaEventCreateWithFlags(&evF, cudaEventDisableTiming);
    cudaEventCreateWithFlags(&evJ, cudaEventDisableTiming);

    // ---- fork: CSR chain on s2, independent of weights/GEMMs ----
    cudaEventRecord(evF, 0);
    cudaStreamWaitEvent(s2, evF, 0);
    zero_int_kernel<<<NBLK, 256, 0, s2>>>();
    deg_count_kernel<<<(E + 255) / 256, 256, 0, s2>>>(ei, E);
    dinv_kernel<<<NBLK, 256, 0, s2>>>();
    scan1_kernel<<<NBLK, 256, 0, s2>>>();
    scan2_kernel<<<1, 256, 0, s2>>>();
    scan3_kernel<<<NBLK, 256, 0, s2>>>();
    fill_csr_kernel<<<(E + 255) / 256, 256, 0, s2>>>(ei, E);
    cudaEventRecord(evJ, s2);

    // ---- main stream: pack + GEMMs ----
    {
        dim3 pg((256 * 256 + 255) / 256, 5);
        pack_weights_kernel<<<pg, 256>>>(W1, Wg1, Wg2, W2, W3);
    }

    // layer 1: h = relu(x @ W1 + b1)   (overlaps the CSR chain)
    hmma_gemm_kernel<true, true><<<GEMM_GRID, 256, SM128>>>(
        x, ph + 0 * WPACK, pl + 0 * WPACK, b1, h, NN, DIN);

    // conv 1 GEMM (still independent of CSR)
    hmma_gemm_kernel<false, false><<<GEMM_GRID, 256, SM256>>>(
        h, ph + 1 * WPACK, pl + 1 * WPACK, nullptr, hW, NN, HH);

    // ---- join: gather needs CSR + dinv ----
    cudaStreamWaitEvent(0, evJ, 0);
    gather_kernel<<<NODE_WARPS, 256>>>(hW, bg1, h);

    // conv 2
    hmma_gemm_kernel<false, false><<<GEMM_GRID, 256, SM256>>>(
        h, ph + 2 * WPACK, pl + 2 * WPACK, nullptr, hW, NN, HH);
    gather_kernel<<<NODE_WARPS, 256>>>(hW, bg2, h);

    // layer 4: hW = relu(h @ W2 + b2)
    hmma_gemm_kernel<true, true><<<GEMM_GRID, 256, SM256>>>(
        h, ph + 3 * WPACK, pl + 3 * WPACK, b2, hW, NN, HH);

    // layer 5 logits: agg = hW @ W3 + b3
    hmma_gemm_kernel<true, false><<<GEMM_GRID, 256, SM256>>>(
        hW, ph + 4 * WPACK, pl + 4 * WPACK, b3, agg, NN, HH);

    // softmax -> out
    softmax_kernel<<<(NN * 32 + 255) / 256, 256>>>(agg, out);
}

// round 16
// speedup vs baseline: 3.3435x; 1.1822x over previous
// R16: identical to R15 submission (infra failure; clean re-measure of fp16 2-product GEMM)
#include <cuda_runtime.h>
#include <cuda_fp16.h>
#include <math.h>

#define NN 50000
#define DIN 128
#define HH 256
#define DOUT 256
#define NBLK 196          // ceil(NN/256)
#define EMAXC 320000

// ---- scratch (device globals; no allocation allowed) ----
__device__ float g_h[NN * HH];
__device__ float g_hW[NN * HH];
__device__ float g_agg[NN * HH];
__device__ float g_dinv[NN];
__device__ int   g_degi[NN];
__device__ int   g_cursor[NN];
__device__ int   g_rowstart[NN];
__device__ int   g_esrc[EMAXC];
__device__ int   g_blocksum[256];

// packed weights: per weight/term: [nh 2][chunk K/32][8KB: n 128 rows x 32 fp16, swizzled]
#define WPACK 131072
__device__ __align__(16) unsigned char g_packh[5 * WPACK];
__device__ __align__(16) unsigned char g_packl[5 * WPACK];

// ============================================================
// mma.sync m16n8k16 fp16 (row.col), fp32 accum + ldmatrix + cp.async
// ============================================================
__device__ __forceinline__ void mma16816(float* c, const unsigned* a, const unsigned* b) {
    asm volatile(
        "mma.sync.aligned.m16n8k16.row.col.f32.f16.f16.f32 "
        "{%0,%1,%2,%3}, {%4,%5,%6,%7}, {%8,%9}, {%0,%1,%2,%3};"
        : "+f"(c[0]), "+f"(c[1]), "+f"(c[2]), "+f"(c[3])
        : "r"(a[0]), "r"(a[1]), "r"(a[2]), "r"(a[3]), "r"(b[0]), "r"(b[1]));
}
__device__ __forceinline__ void ldsm4(unsigned* r, unsigned addr) {
    asm volatile("ldmatrix.sync.aligned.m8n8.x4.shared.b16 {%0,%1,%2,%3}, [%4];"
                 : "=r"(r[0]), "=r"(r[1]), "=r"(r[2]), "=r"(r[3]) : "r"(addr));
}
__device__ __forceinline__ void cpasync16(unsigned saddr, const void* gaddr) {
    asm volatile("cp.async.cg.shared.global [%0], [%1], 16;" :: "r"(saddr), "l"(gaddr));
}
__device__ __forceinline__ void cpcommit() { asm volatile("cp.async.commit_group;"); }
__device__ __forceinline__ void cpwait0() { asm volatile("cp.async.wait_group 0;" ::: "memory"); }

__device__ __forceinline__ unsigned pack_h2(__half x, __half y) {
    return ((unsigned)__half_as_ushort(y) << 16) | __half_as_ushort(x);
}
// swizzled byte offset within an 8KB tile: row (0..127) of 64B, granule g (0..3), byte b (0..15)
__device__ __host__ __forceinline__ int swz_off(int row, int g, int b) {
    return row * 64 + ((g ^ ((row >> 1) & 3)) << 4) + b;
}

// ============================================================
// weight prepack: W[K,256] fp32 -> hi/lo fp16 in ldmatrix-ready [n][k] swizzled tiles
// ============================================================
__global__ void pack_weights_kernel(const float* W1, const float* Wg1, const float* Wg2,
                                    const float* W2, const float* W3) {
    int wi = blockIdx.y;
    const float* W = (wi == 0) ? W1 : (wi == 1) ? Wg1 : (wi == 2) ? Wg2 : (wi == 3) ? W2 : W3;
    int K = (wi == 0) ? DIN : HH;
    int i = blockIdx.x * blockDim.x + threadIdx.x;
    if (i >= K * 256) return;
    int k = i >> 8, n = i & 255;
    float w = W[i];
    __half h = __float2half_rn(w);
    __half l = __float2half_rn(w - __half2float(h));
    int c = k >> 5, kl = k & 31;
    int kp = kl >> 1, hl = kl & 1;
    int nh = n >> 7, nl = n & 127;
    size_t off = (size_t)wi * WPACK + ((size_t)(nh * (K >> 5) + c)) * 8192
               + swz_off(nl, kp >> 2, (kp & 3) * 4 + hl * 2);
    *(__half*)(g_packh + off) = h;
    *(__half*)(g_packl + off) = l;
}

// ============================================================
// HMMA GEMM: one CTA computes 128 rows x ALL 256 cols.
// A (fp16 hi only) staged in full (chunks x 8KB); B (hi/lo) streamed per
// column-half with cp.async double buffering. 2-product scheme:
//   C = Ah*Bh + Ah*Bl  (drops A's quantization correction, ~2^-12 rel)
// 8 warps (2M x 4N), warp m64n32, BK=32.
// ============================================================
template <bool BIAS, bool RELU>
__global__ __launch_bounds__(256, 1) void hmma_gemm_kernel(
    const float* __restrict__ A, const unsigned char* __restrict__ Bhp,
    const unsigned char* __restrict__ Blp, const float* __restrict__ bias,
    float* __restrict__ C, int M, int K)
{
    extern __shared__ __align__(16) unsigned char smem[];
    unsigned sbase = (unsigned)__cvta_generic_to_shared(smem);

    int tid = threadIdx.x;
    int lane = tid & 31;
    int wid = tid >> 5;
    int wm = wid & 1;
    int wn = wid >> 1;
    int row0 = blockIdx.x * 128;
    int chunks = K >> 5;
    unsigned bbase = (unsigned)(chunks * 8192);   // B region after A (hi only)

    int skp = tid & 15;
    int srow = tid >> 4;
    int sAoff[8];
    bool sOK[8];
#pragma unroll
    for (int it = 0; it < 8; it++) {
        int r = srow + it * 16;
        sAoff[it] = swz_off(r, skp >> 2, (skp & 3) * 4);
        sOK[it] = (row0 + r) < M;
    }

    unsigned bso0 = tid * 16, bso1 = (tid + 256) * 16;

    unsigned offA[4], offB[2];
    {
        int rA = wm * 64 + (lane & 15);
        int gA = lane >> 4;
#pragma unroll
        for (int mt = 0; mt < 4; mt++) offA[mt] = swz_off(rA + mt * 16, gA, 0);
        int nB = wn * 32 + ((lane >> 4) << 3) + (lane & 7);
        int gB = (lane >> 3) & 1;
#pragma unroll
        for (int np = 0; np < 2; np++) offB[np] = swz_off(nB + np * 16, gB, 0);
    }

    // kick off first B copy (hi 8KB + lo 8KB), then stage ALL of A hi
    cpasync16(sbase + bbase + bso0, Bhp + bso0);
    cpasync16(sbase + bbase + bso1, Bhp + bso1);
    cpasync16(sbase + bbase + 8192 + bso0, Blp + bso0);
    cpasync16(sbase + bbase + 8192 + bso1, Blp + bso1);
    cpcommit();

    for (int c = 0; c < chunks; c++) {
        unsigned abase = c * 8192;
#pragma unroll
        for (int it = 0; it < 8; it++) {
            int r = srow + it * 16;
            float2 v = make_float2(0.f, 0.f);
            if (sOK[it]) v = *(const float2*)&A[(size_t)(row0 + r) * K + c * 32 + skp * 2];
            __half h0 = __float2half_rn(v.x), h1 = __float2half_rn(v.y);
            *(unsigned*)(smem + abase + sAoff[it]) = pack_h2(h0, h1);
        }
    }

    float acc[4][4][4];
#pragma unroll
    for (int mt = 0; mt < 4; mt++)
#pragma unroll
        for (int nt = 0; nt < 4; nt++)
#pragma unroll
            for (int q = 0; q < 4; q++) acc[mt][nt][q] = 0.0f;

    int total = 2 * chunks;
    for (int t = 0; t < total; t++) {
        int nh = (t >= chunks) ? 1 : 0;
        int c = t - nh * chunks;
        unsigned cbuf = bbase + (unsigned)((t & 1) * 16384);
        unsigned nbuf = bbase + (unsigned)(((t + 1) & 1) * 16384);
        bool more = (t + 1) < total;

        cpwait0();
        __syncthreads();

        if (more) {
            const unsigned char* bh = Bhp + (size_t)(t + 1) * 8192;
            const unsigned char* bl = Blp + (size_t)(t + 1) * 8192;
            cpasync16(sbase + nbuf + bso0, bh + bso0);
            cpasync16(sbase + nbuf + bso1, bh + bso1);
            cpasync16(sbase + nbuf + 8192 + bso0, bl + bso0);
            cpasync16(sbase + nbuf + 8192 + bso1, bl + bso1);
            cpcommit();
        }

        unsigned abase = c * 8192;
#pragma unroll
        for (int j = 0; j < 2; j++) {
            unsigned jx = j ? 32u : 0u;
            unsigned bfh[2][4], bfl[2][4];
#pragma unroll
            for (int np = 0; np < 2; np++) {
                ldsm4(bfh[np], sbase + cbuf + (offB[np] ^ jx));
                ldsm4(bfl[np], sbase + cbuf + 8192 + (offB[np] ^ jx));
            }
            unsigned afh[4][4];
#pragma unroll
            for (int mt = 0; mt < 4; mt++)
                ldsm4(afh[mt], sbase + abase + (offA[mt] ^ jx));
#pragma unroll
            for (int mt = 0; mt < 4; mt++)
#pragma unroll
                for (int nt = 0; nt < 4; nt++) {
                    const unsigned* bh = &bfh[nt >> 1][(nt & 1) * 2];
                    const unsigned* bl = &bfl[nt >> 1][(nt & 1) * 2];
                    mma16816(acc[mt][nt], afh[mt], bh);
                    mma16816(acc[mt][nt], afh[mt], bl);
                }
        }

        if (c == chunks - 1) {
            int colBlock = nh * 128;
#pragma unroll
            for (int mt = 0; mt < 4; mt++) {
                int r0 = row0 + wm * 64 + mt * 16 + (lane >> 2);
#pragma unroll
                for (int nt = 0; nt < 4; nt++) {
                    int col = colBlock + wn * 32 + nt * 8 + (lane & 3) * 2;
                    float b0 = 0.f, b1 = 0.f;
                    if (BIAS) { b0 = bias[col]; b1 = bias[col + 1]; }
#pragma unroll
                    for (int hh = 0; hh < 2; hh++) {
                        int r = r0 + hh * 8;
                        if (r >= M) continue;
                        float v0 = acc[mt][nt][hh * 2 + 0];
                        float v1 = acc[mt][nt][hh * 2 + 1];
                        if (BIAS) { v0 += b0; v1 += b1; }
                        if (RELU) { v0 = fmaxf(v0, 0.f); v1 = fmaxf(v1, 0.f); }
                        *(float2*)&C[(size_t)r * 256 + col] = make_float2(v0, v1);
                    }
#pragma unroll
                    for (int q = 0; q < 4; q++) acc[mt][nt][q] = 0.0f;
                }
            }
        }
    }
}

// ============================================================
// CSR build (edge_index INT32: src = ei[e], dst = ei[E+e])
// ============================================================
__global__ void zero_int_kernel() {
    int i = blockIdx.x * blockDim.x + threadIdx.x;
    if (i < NN) { g_degi[i] = 0; g_cursor[i] = 0; }
}
__global__ void deg_count_kernel(const int* __restrict__ ei, int E) {
    int e = blockIdx.x * blockDim.x + threadIdx.x;
    if (e < E) {
        int d = ei[E + e];
        if ((unsigned)d < (unsigned)NN) atomicAdd(&g_degi[d], 1);
    }
}
__global__ void dinv_kernel() {
    int i = blockIdx.x * blockDim.x + threadIdx.x;
    if (i < NN) g_dinv[i] = rsqrtf((float)g_degi[i] + 1.0f);
}
__global__ void scan1_kernel() {
    __shared__ int sh[256];
    int t = threadIdx.x;
    int i = blockIdx.x * 256 + t;
    int v = (i < NN) ? g_degi[i] : 0;
    sh[t] = v;
    __syncthreads();
#pragma unroll
    for (int off = 1; off < 256; off <<= 1) {
        int x = (t >= off) ? sh[t - off] : 0;
        __syncthreads();
        sh[t] += x;
        __syncthreads();
    }
    if (i < NN) g_rowstart[i] = sh[t] - v;
    if (t == 255) g_blocksum[blockIdx.x] = sh[255];
}
__global__ void scan2_kernel() {
    __shared__ int sh[256];
    int t = threadIdx.x;
    int v = (t < NBLK) ? g_blocksum[t] : 0;
    sh[t] = v;
    __syncthreads();
#pragma unroll
    for (int off = 1; off < 256; off <<= 1) {
        int x = (t >= off) ? sh[t - off] : 0;
        __syncthreads();
        sh[t] += x;
        __syncthreads();
    }
    if (t < NBLK) g_blocksum[t] = sh[t] - v;
}
__global__ void scan3_kernel() {
    int i = blockIdx.x * blockDim.x + threadIdx.x;
    if (i < NN) g_rowstart[i] += g_blocksum[i >> 8];
}
__global__ void fill_csr_kernel(const int* __restrict__ ei, int E) {
    int e = blockIdx.x * blockDim.x + threadIdx.x;
    if (e >= E) return;
    int s = ei[e];
    int d = ei[E + e];
    if ((unsigned)s >= (unsigned)NN || (unsigned)d >= (unsigned)NN) return;
    int pos = g_rowstart[d] + atomicAdd(&g_cursor[d], 1);
    if (pos < EMAXC) g_esrc[pos] = s;
}

// ============================================================
// fused gather: h[d] = relu( sum hW[s]*dinv[s]*dinv[d] + hW[d]*dinv[d]^2 + bias )
// ============================================================
__global__ void gather_kernel(const float* __restrict__ hW,
                              const float* __restrict__ bias,
                              float* __restrict__ hout)
{
    int node = (blockIdx.x * blockDim.x + threadIdx.x) >> 5;
    int lane = threadIdx.x & 31;
    if (node >= NN) return;
    float dv = g_dinv[node];
    int base = g_rowstart[node];
    int cnt = g_degi[node];

    const float4* sp = (const float4*)(hW + (size_t)node * HH);
    float4 a0 = sp[lane];
    float4 a1 = sp[lane + 32];
    float ss = dv * dv;
    a0.x *= ss; a0.y *= ss; a0.z *= ss; a0.w *= ss;
    a1.x *= ss; a1.y *= ss; a1.z *= ss; a1.w *= ss;

#pragma unroll 2
    for (int j = 0; j < cnt; j++) {
        int s = g_esrc[base + j];
        float w = g_dinv[s] * dv;
        const float4* q = (const float4*)(hW + (size_t)s * HH);
        float4 v0 = q[lane];
        float4 v1 = q[lane + 32];
        a0.x += v0.x * w; a0.y += v0.y * w; a0.z += v0.z * w; a0.w += v0.w * w;
        a1.x += v1.x * w; a1.y += v1.y * w; a1.z += v1.z * w; a1.w += v1.w * w;
    }

    float4 b0 = ((const float4*)bias)[lane];
    float4 b1 = ((const float4*)bias)[lane + 32];
    a0.x = fmaxf(a0.x + b0.x, 0.f); a0.y = fmaxf(a0.y + b0.y, 0.f);
    a0.z = fmaxf(a0.z + b0.z, 0.f); a0.w = fmaxf(a0.w + b0.w, 0.f);
    a1.x = fmaxf(a1.x + b1.x, 0.f); a1.y = fmaxf(a1.y + b1.y, 0.f);
    a1.z = fmaxf(a1.z + b1.z, 0.f); a1.w = fmaxf(a1.w + b1.w, 0.f);

    float4* op = (float4*)(hout + (size_t)node * HH);
    op[lane] = a0;
    op[lane + 32] = a1;
}

// ============================================================
// softmax per row, one warp per row
// ============================================================
__global__ void softmax_kernel(const float* __restrict__ in, float* __restrict__ out) {
    int warp = (blockIdx.x * blockDim.x + threadIdx.x) >> 5;
    int lane = threadIdx.x & 31;
    if (warp >= NN) return;
    const float4* ip = (const float4*)(in + (size_t)warp * DOUT);
    float4 a = ip[lane];
    float4 b = ip[lane + 32];
    float m = fmaxf(fmaxf(fmaxf(a.x, a.y), fmaxf(a.z, a.w)),
                    fmaxf(fmaxf(b.x, b.y), fmaxf(b.z, b.w)));
#pragma unroll
    for (int o = 16; o > 0; o >>= 1)
        m = fmaxf(m, __shfl_xor_sync(0xFFFFFFFFu, m, o));
    a.x = __expf(a.x - m); a.y = __expf(a.y - m); a.z = __expf(a.z - m); a.w = __expf(a.w - m);
    b.x = __expf(b.x - m); b.y = __expf(b.y - m); b.z = __expf(b.z - m); b.w = __expf(b.w - m);
    float s = a.x + a.y + a.z + a.w + b.x + b.y + b.z + b.w;
#pragma unroll
    for (int o = 16; o > 0; o >>= 1)
        s += __shfl_xor_sync(0xFFFFFFFFu, s, o);
    float inv = 1.0f / s;
    a.x *= inv; a.y *= inv; a.z *= inv; a.w *= inv;
    b.x *= inv; b.y *= inv; b.z *= inv; b.w *= inv;
    float4* op = (float4*)(out + (size_t)warp * DOUT);
    op[lane] = a;
    op[lane + 32] = b;
}

// ============================================================
// host launch — fork CSR chain onto a side stream, join before gather-1
// ============================================================
extern "C" void kernel_launch(void* const* d_in, const int* in_sizes, int n_in,
                              void* d_out, int out_size)
{
    const float* x    = (const float*)d_in[0];
    const int* ei     = (const int*)d_in[1];   // int32
    const float* W1  = (const float*)d_in[2];
    const float* b1  = (const float*)d_in[3];
    const float* Wg1 = (const float*)d_in[4];
    const float* bg1 = (const float*)d_in[5];
    const float* Wg2 = (const float*)d_in[6];
    const float* bg2 = (const float*)d_in[7];
    const float* W2  = (const float*)d_in[8];
    const float* b2  = (const float*)d_in[9];
    const float* W3  = (const float*)d_in[10];
    const float* b3  = (const float*)d_in[11];
    float* out = (float*)d_out;

    int E = in_sizes[1] / 2;

    float *h, *hW, *agg;
    unsigned char *ph, *pl;
    cudaGetSymbolAddress((void**)&h, g_h);
    cudaGetSymbolAddress((void**)&hW, g_hW);
    cudaGetSymbolAddress((void**)&agg, g_agg);
    cudaGetSymbolAddress((void**)&ph, g_packh);
    cudaGetSymbolAddress((void**)&pl, g_packl);

    const int SM128 = 4 * 8192 + 32768;   // K=128: 64KB
    const int SM256 = 8 * 8192 + 32768;   // K=256: 96KB
    cudaFuncSetAttribute(hmma_gemm_kernel<true, true>,
                         cudaFuncAttributeMaxDynamicSharedMemorySize, SM256);
    cudaFuncSetAttribute(hmma_gemm_kernel<false, false>,
                         cudaFuncAttributeMaxDynamicSharedMemorySize, SM256);
    cudaFuncSetAttribute(hmma_gemm_kernel<true, false>,
                         cudaFuncAttributeMaxDynamicSharedMemorySize, SM256);

    const int GEMM_GRID = (NN + 127) / 128;
    const int NODE_WARPS = (NN * 32 + 255) / 256;

    cudaStream_t s2;
    cudaEvent_t evF, evJ;
    cudaStreamCreateWithFlags(&s2, cudaStreamNonBlocking);
    cudaEventCreateWithFlags(&evF, cudaEventDisableTiming);
    cudaEventCreateWithFlags(&evJ, cudaEventDisableTiming);

    // ---- fork: CSR chain on s2 ----
    cudaEventRecord(evF, 0);
    cudaStreamWaitEvent(s2, evF, 0);
    zero_int_kernel<<<NBLK, 256, 0, s2>>>();
    deg_count_kernel<<<(E + 255) / 256, 256, 0, s2>>>(ei, E);
    dinv_kernel<<<NBLK, 256, 0, s2>>>();
    scan1_kernel<<<NBLK, 256, 0, s2>>>();
    scan2_kernel<<<1, 256, 0, s2>>>();
    scan3_kernel<<<NBLK, 256, 0, s2>>>();
    fill_csr_kernel<<<(E + 255) / 256, 256, 0, s2>>>(ei, E);
    cudaEventRecord(evJ, s2);

    // ---- main stream: pack + GEMMs ----
    {
        dim3 pg((256 * 256 + 255) / 256, 5);
        pack_weights_kernel<<<pg, 256>>>(W1, Wg1, Wg2, W2, W3);
    }

    // layer 1: h = relu(x @ W1 + b1)
    hmma_gemm_kernel<true, true><<<GEMM_GRID, 256, SM128>>>(
        x, ph + 0 * WPACK, pl + 0 * WPACK, b1, h, NN, DIN);

    // conv 1 GEMM
    hmma_gemm_kernel<false, false><<<GEMM_GRID, 256, SM256>>>(
        h, ph + 1 * WPACK, pl + 1 * WPACK, nullptr, hW, NN, HH);

    // join: gather needs CSR + dinv
    cudaStreamWaitEvent(0, evJ, 0);
    gather_kernel<<<NODE_WARPS, 256>>>(hW, bg1, h);

    // conv 2
    hmma_gemm_kernel<false, false><<<GEMM_GRID, 256, SM256>>>(
        h, ph + 2 * WPACK, pl + 2 * WPACK, nullptr, hW, NN, HH);
    gather_kernel<<<NODE_WARPS, 256>>>(hW, bg2, h);

    // layer 4: hW = relu(h @ W2 + b2)
    hmma_gemm_kernel<true, true><<<GEMM_GRID, 256, SM256>>>(
        h, ph + 3 * WPACK, pl + 3 * WPACK, b2, hW, NN, HH);

    // layer 5 logits: agg = hW @ W3 + b3
    hmma_gemm_kernel<true, false><<<GEMM_GRID, 256, SM256>>>(
        hW, ph + 4 * WPACK, pl + 4 * WPACK, b3, agg, NN, HH);

    // softmax -> out
    softmax_kernel<<<(NN * 32 + 255) / 256, 256>>>(agg, out);
}

// round 17
// speedup vs baseline: 4.6628x; 1.3946x over previous
// R17: 1-product pure-fp16 GEMM (A fp16, B fp16), 2 CTA/SM
#include <cuda_runtime.h>
#include <cuda_fp16.h>
#include <math.h>

#define NN 50000
#define DIN 128
#define HH 256
#define DOUT 256
#define NBLK 196          // ceil(NN/256)
#define EMAXC 320000

// ---- scratch (device globals; no allocation allowed) ----
__device__ float g_h[NN * HH];
__device__ float g_hW[NN * HH];
__device__ float g_agg[NN * HH];
__device__ float g_dinv[NN];
__device__ int   g_degi[NN];
__device__ int   g_cursor[NN];
__device__ int   g_rowstart[NN];
__device__ int   g_esrc[EMAXC];
__device__ int   g_blocksum[256];

// packed weights: per weight: [nh 2][chunk K/32][8KB: n 128 rows x 32 fp16, swizzled]
#define WPACK 131072
__device__ __align__(16) unsigned char g_packh[5 * WPACK];

// ============================================================
// mma.sync m16n8k16 fp16 (row.col), fp32 accum + ldmatrix + cp.async
// ============================================================
__device__ __forceinline__ void mma16816(float* c, const unsigned* a, const unsigned* b) {
    asm volatile(
        "mma.sync.aligned.m16n8k16.row.col.f32.f16.f16.f32 "
        "{%0,%1,%2,%3}, {%4,%5,%6,%7}, {%8,%9}, {%0,%1,%2,%3};"
        : "+f"(c[0]), "+f"(c[1]), "+f"(c[2]), "+f"(c[3])
        : "r"(a[0]), "r"(a[1]), "r"(a[2]), "r"(a[3]), "r"(b[0]), "r"(b[1]));
}
__device__ __forceinline__ void ldsm4(unsigned* r, unsigned addr) {
    asm volatile("ldmatrix.sync.aligned.m8n8.x4.shared.b16 {%0,%1,%2,%3}, [%4];"
                 : "=r"(r[0]), "=r"(r[1]), "=r"(r[2]), "=r"(r[3]) : "r"(addr));
}
__device__ __forceinline__ void cpasync16(unsigned saddr, const void* gaddr) {
    asm volatile("cp.async.cg.shared.global [%0], [%1], 16;" :: "r"(saddr), "l"(gaddr));
}
__device__ __forceinline__ void cpcommit() { asm volatile("cp.async.commit_group;"); }
__device__ __forceinline__ void cpwait0() { asm volatile("cp.async.wait_group 0;" ::: "memory"); }

__device__ __forceinline__ unsigned pack_h2(__half x, __half y) {
    return ((unsigned)__half_as_ushort(y) << 16) | __half_as_ushort(x);
}
// swizzled byte offset within an 8KB tile: row (0..127) of 64B, granule g (0..3), byte b (0..15)
__device__ __host__ __forceinline__ int swz_off(int row, int g, int b) {
    return row * 64 + ((g ^ ((row >> 1) & 3)) << 4) + b;
}

// ============================================================
// weight prepack: W[K,256] fp32 -> fp16 in ldmatrix-ready [n][k] swizzled tiles
// ============================================================
__global__ void pack_weights_kernel(const float* W1, const float* Wg1, const float* Wg2,
                                    const float* W2, const float* W3) {
    int wi = blockIdx.y;
    const float* W = (wi == 0) ? W1 : (wi == 1) ? Wg1 : (wi == 2) ? Wg2 : (wi == 3) ? W2 : W3;
    int K = (wi == 0) ? DIN : HH;
    int i = blockIdx.x * blockDim.x + threadIdx.x;
    if (i >= K * 256) return;
    int k = i >> 8, n = i & 255;
    __half h = __float2half_rn(W[i]);
    int c = k >> 5, kl = k & 31;
    int kp = kl >> 1, hl = kl & 1;
    int nh = n >> 7, nl = n & 127;
    size_t off = (size_t)wi * WPACK + ((size_t)(nh * (K >> 5) + c)) * 8192
               + swz_off(nl, kp >> 2, (kp & 3) * 4 + hl * 2);
    *(__half*)(g_packh + off) = h;
}

// ============================================================
// HMMA GEMM: one CTA computes 128 rows x ALL 256 cols, pure fp16 operands.
// A staged in full (chunks x 8KB); B streamed per column-half with cp.async
// double buffering (2 x 8KB). 8 warps (2M x 4N), warp m64n32, BK=32.
// smem: K=128 -> 48KB, K=256 -> 80KB  => 2 CTAs/SM.
// ============================================================
template <bool BIAS, bool RELU>
__global__ __launch_bounds__(256, 2) void hmma_gemm_kernel(
    const float* __restrict__ A, const unsigned char* __restrict__ Bhp,
    const float* __restrict__ bias, float* __restrict__ C, int M, int K)
{
    extern __shared__ __align__(16) unsigned char smem[];
    unsigned sbase = (unsigned)__cvta_generic_to_shared(smem);

    int tid = threadIdx.x;
    int lane = tid & 31;
    int wid = tid >> 5;
    int wm = wid & 1;
    int wn = wid >> 1;
    int row0 = blockIdx.x * 128;
    int chunks = K >> 5;
    unsigned bbase = (unsigned)(chunks * 8192);   // B region after A

    int skp = tid & 15;
    int srow = tid >> 4;
    int sAoff[8];
    bool sOK[8];
#pragma unroll
    for (int it = 0; it < 8; it++) {
        int r = srow + it * 16;
        sAoff[it] = swz_off(r, skp >> 2, (skp & 3) * 4);
        sOK[it] = (row0 + r) < M;
    }

    // B cp.async geometry: 8KB tile = 512 x 16B; 256 threads x 2
    unsigned bso0 = tid * 16, bso1 = (tid + 256) * 16;

    unsigned offA[4], offB[2];
    {
        int rA = wm * 64 + (lane & 15);
        int gA = lane >> 4;
#pragma unroll
        for (int mt = 0; mt < 4; mt++) offA[mt] = swz_off(rA + mt * 16, gA, 0);
        int nB = wn * 32 + ((lane >> 4) << 3) + (lane & 7);
        int gB = (lane >> 3) & 1;
#pragma unroll
        for (int np = 0; np < 2; np++) offB[np] = swz_off(nB + np * 16, gB, 0);
    }

    // kick off first B copy, then stage ALL of A (overlaps the copy)
    cpasync16(sbase + bbase + bso0, Bhp + bso0);
    cpasync16(sbase + bbase + bso1, Bhp + bso1);
    cpcommit();

    for (int c = 0; c < chunks; c++) {
        unsigned abase = c * 8192;
#pragma unroll
        for (int it = 0; it < 8; it++) {
            int r = srow + it * 16;
            float2 v = make_float2(0.f, 0.f);
            if (sOK[it]) v = *(const float2*)&A[(size_t)(row0 + r) * K + c * 32 + skp * 2];
            *(unsigned*)(smem + abase + sAoff[it]) =
                pack_h2(__float2half_rn(v.x), __float2half_rn(v.y));
        }
    }

    float acc[4][4][4];
#pragma unroll
    for (int mt = 0; mt < 4; mt++)
#pragma unroll
        for (int nt = 0; nt < 4; nt++)
#pragma unroll
            for (int q = 0; q < 4; q++) acc[mt][nt][q] = 0.0f;

    int total = 2 * chunks;
    for (int t = 0; t < total; t++) {
        int nh = (t >= chunks) ? 1 : 0;
        int c = t - nh * chunks;
        unsigned cbuf = bbase + (unsigned)((t & 1) * 8192);
        unsigned nbuf = bbase + (unsigned)(((t + 1) & 1) * 8192);
        bool more = (t + 1) < total;

        cpwait0();
        __syncthreads();

        if (more) {
            const unsigned char* bh = Bhp + (size_t)(t + 1) * 8192;
            cpasync16(sbase + nbuf + bso0, bh + bso0);
            cpasync16(sbase + nbuf + bso1, bh + bso1);
            cpcommit();
        }

        unsigned abase = c * 8192;
#pragma unroll
        for (int j = 0; j < 2; j++) {
            unsigned jx = j ? 32u : 0u;
            unsigned bfh[2][4];
#pragma unroll
            for (int np = 0; np < 2; np++)
                ldsm4(bfh[np], sbase + cbuf + (offB[np] ^ jx));
            unsigned afh[4][4];
#pragma unroll
            for (int mt = 0; mt < 4; mt++)
                ldsm4(afh[mt], sbase + abase + (offA[mt] ^ jx));
#pragma unroll
            for (int mt = 0; mt < 4; mt++)
#pragma unroll
                for (int nt = 0; nt < 4; nt++)
                    mma16816(acc[mt][nt], afh[mt], &bfh[nt >> 1][(nt & 1) * 2]);
        }

        if (c == chunks - 1) {
            int colBlock = nh * 128;
#pragma unroll
            for (int mt = 0; mt < 4; mt++) {
                int r0 = row0 + wm * 64 + mt * 16 + (lane >> 2);
#pragma unroll
                for (int nt = 0; nt < 4; nt++) {
                    int col = colBlock + wn * 32 + nt * 8 + (lane & 3) * 2;
                    float b0 = 0.f, b1 = 0.f;
                    if (BIAS) { b0 = bias[col]; b1 = bias[col + 1]; }
#pragma unroll
                    for (int hh = 0; hh < 2; hh++) {
                        int r = r0 + hh * 8;
                        if (r >= M) continue;
                        float v0 = acc[mt][nt][hh * 2 + 0];
                        float v1 = acc[mt][nt][hh * 2 + 1];
                        if (BIAS) { v0 += b0; v1 += b1; }
                        if (RELU) { v0 = fmaxf(v0, 0.f); v1 = fmaxf(v1, 0.f); }
                        *(float2*)&C[(size_t)r * 256 + col] = make_float2(v0, v1);
                    }
#pragma unroll
                    for (int q = 0; q < 4; q++) acc[mt][nt][q] = 0.0f;
                }
            }
        }
    }
}

// ============================================================
// CSR build (edge_index INT32: src = ei[e], dst = ei[E+e])
// ============================================================
__global__ void zero_int_kernel() {
    int i = blockIdx.x * blockDim.x + threadIdx.x;
    if (i < NN) { g_degi[i] = 0; g_cursor[i] = 0; }
}
__global__ void deg_count_kernel(const int* __restrict__ ei, int E) {
    int e = blockIdx.x * blockDim.x + threadIdx.x;
    if (e < E) {
        int d = ei[E + e];
        if ((unsigned)d < (unsigned)NN) atomicAdd(&g_degi[d], 1);
    }
}
__global__ void dinv_kernel() {
    int i = blockIdx.x * blockDim.x + threadIdx.x;
    if (i < NN) g_dinv[i] = rsqrtf((float)g_degi[i] + 1.0f);
}
__global__ void scan1_kernel() {
    __shared__ int sh[256];
    int t = threadIdx.x;
    int i = blockIdx.x * 256 + t;
    int v = (i < NN) ? g_degi[i] : 0;
    sh[t] = v;
    __syncthreads();
#pragma unroll
    for (int off = 1; off < 256; off <<= 1) {
        int x = (t >= off) ? sh[t - off] : 0;
        __syncthreads();
        sh[t] += x;
        __syncthreads();
    }
    if (i < NN) g_rowstart[i] = sh[t] - v;
    if (t == 255) g_blocksum[blockIdx.x] = sh[255];
}
__global__ void scan2_kernel() {
    __shared__ int sh[256];
    int t = threadIdx.x;
    int v = (t < NBLK) ? g_blocksum[t] : 0;
    sh[t] = v;
    __syncthreads();
#pragma unroll
    for (int off = 1; off < 256; off <<= 1) {
        int x = (t >= off) ? sh[t - off] : 0;
        __syncthreads();
        sh[t] += x;
        __syncthreads();
    }
    if (t < NBLK) g_blocksum[t] = sh[t] - v;
}
__global__ void scan3_kernel() {
    int i = blockIdx.x * blockDim.x + threadIdx.x;
    if (i < NN) g_rowstart[i] += g_blocksum[i >> 8];
}
__global__ void fill_csr_kernel(const int* __restrict__ ei, int E) {
    int e = blockIdx.x * blockDim.x + threadIdx.x;
    if (e >= E) return;
    int s = ei[e];
    int d = ei[E + e];
    if ((unsigned)s >= (unsigned)NN || (unsigned)d >= (unsigned)NN) return;
    int pos = g_rowstart[d] + atomicAdd(&g_cursor[d], 1);
    if (pos < EMAXC) g_esrc[pos] = s;
}

// ============================================================
// fused gather: h[d] = relu( sum hW[s]*dinv[s]*dinv[d] + hW[d]*dinv[d]^2 + bias )
// ============================================================
__global__ void gather_kernel(const float* __restrict__ hW,
                              const float* __restrict__ bias,
                              float* __restrict__ hout)
{
    int node = (blockIdx.x * blockDim.x + threadIdx.x) >> 5;
    int lane = threadIdx.x & 31;
    if (node >= NN) return;
    float dv = g_dinv[node];
    int base = g_rowstart[node];
    int cnt = g_degi[node];

    const float4* sp = (const float4*)(hW + (size_t)node * HH);
    float4 a0 = sp[lane];
    float4 a1 = sp[lane + 32];
    float ss = dv * dv;
    a0.x *= ss; a0.y *= ss; a0.z *= ss; a0.w *= ss;
    a1.x *= ss; a1.y *= ss; a1.z *= ss; a1.w *= ss;

#pragma unroll 2
    for (int j = 0; j < cnt; j++) {
        int s = g_esrc[base + j];
        float w = g_dinv[s] * dv;
        const float4* q = (const float4*)(hW + (size_t)s * HH);
        float4 v0 = q[lane];
        float4 v1 = q[lane + 32];
        a0.x += v0.x * w; a0.y += v0.y * w; a0.z += v0.z * w; a0.w += v0.w * w;
        a1.x += v1.x * w; a1.y += v1.y * w; a1.z += v1.z * w; a1.w += v1.w * w;
    }

    float4 b0 = ((const float4*)bias)[lane];
    float4 b1 = ((const float4*)bias)[lane + 32];
    a0.x = fmaxf(a0.x + b0.x, 0.f); a0.y = fmaxf(a0.y + b0.y, 0.f);
    a0.z = fmaxf(a0.z + b0.z, 0.f); a0.w = fmaxf(a0.w + b0.w, 0.f);
    a1.x = fmaxf(a1.x + b1.x, 0.f); a1.y = fmaxf(a1.y + b1.y, 0.f);
    a1.z = fmaxf(a1.z + b1.z, 0.f); a1.w = fmaxf(a1.w + b1.w, 0.f);

    float4* op = (float4*)(hout + (size_t)node * HH);
    op[lane] = a0;
    op[lane + 32] = a1;
}

// ============================================================
// softmax per row, one warp per row
// ============================================================
__global__ void softmax_kernel(const float* __restrict__ in, float* __restrict__ out) {
    int warp = (blockIdx.x * blockDim.x + threadIdx.x) >> 5;
    int lane = threadIdx.x & 31;
    if (warp >= NN) return;
    const float4* ip = (const float4*)(in + (size_t)warp * DOUT);
    float4 a = ip[lane];
    float4 b = ip[lane + 32];
    float m = fmaxf(fmaxf(fmaxf(a.x, a.y), fmaxf(a.z, a.w)),
                    fmaxf(fmaxf(b.x, b.y), fmaxf(b.z, b.w)));
#pragma unroll
    for (int o = 16; o > 0; o >>= 1)
        m = fmaxf(m, __shfl_xor_sync(0xFFFFFFFFu, m, o));
    a.x = __expf(a.x - m); a.y = __expf(a.y - m); a.z = __expf(a.z - m); a.w = __expf(a.w - m);
    b.x = __expf(b.x - m); b.y = __expf(b.y - m); b.z = __expf(b.z - m); b.w = __expf(b.w - m);
    float s = a.x + a.y + a.z + a.w + b.x + b.y + b.z + b.w;
#pragma unroll
    for (int o = 16; o > 0; o >>= 1)
        s += __shfl_xor_sync(0xFFFFFFFFu, s, o);
    float inv = 1.0f / s;
    a.x *= inv; a.y *= inv; a.z *= inv; a.w *= inv;
    b.x *= inv; b.y *= inv; b.z *= inv; b.w *= inv;
    float4* op = (float4*)(out + (size_t)warp * DOUT);
    op[lane] = a;
    op[lane + 32] = b;
}

// ============================================================
// host launch — fork CSR chain onto a side stream, join before gather-1
// ============================================================
extern "C" void kernel_launch(void* const* d_in, const int* in_sizes, int n_in,
                              void* d_out, int out_size)
{
    const float* x    = (const float*)d_in[0];
    const int* ei     = (const int*)d_in[1];   // int32
    const float* W1  = (const float*)d_in[2];
    const float* b1  = (const float*)d_in[3];
    const float* Wg1 = (const float*)d_in[4];
    const float* bg1 = (const float*)d_in[5];
    const float* Wg2 = (const float*)d_in[6];
    const float* bg2 = (const float*)d_in[7];
    const float* W2  = (const float*)d_in[8];
    const float* b2  = (const float*)d_in[9];
    const float* W3  = (const float*)d_in[10];
    const float* b3  = (const float*)d_in[11];
    float* out = (float*)d_out;

    int E = in_sizes[1] / 2;

    float *h, *hW, *agg;
    unsigned char *ph;
    cudaGetSymbolAddress((void**)&h, g_h);
    cudaGetSymbolAddress((void**)&hW, g_hW);
    cudaGetSymbolAddress((void**)&agg, g_agg);
    cudaGetSymbolAddress((void**)&ph, g_packh);

    const int SM128 = 4 * 8192 + 16384;   // K=128: 48KB
    const int SM256 = 8 * 8192 + 16384;   // K=256: 80KB
    cudaFuncSetAttribute(hmma_gemm_kernel<true, true>,
                         cudaFuncAttributeMaxDynamicSharedMemorySize, SM256);
    cudaFuncSetAttribute(hmma_gemm_kernel<false, false>,
                         cudaFuncAttributeMaxDynamicSharedMemorySize, SM256);
    cudaFuncSetAttribute(hmma_gemm_kernel<true, false>,
                         cudaFuncAttributeMaxDynamicSharedMemorySize, SM256);

    const int GEMM_GRID = (NN + 127) / 128;
    const int NODE_WARPS = (NN * 32 + 255) / 256;

    cudaStream_t s2;
    cudaEvent_t evF, evJ;
    cudaStreamCreateWithFlags(&s2, cudaStreamNonBlocking);
    cudaEventCreateWithFlags(&evF, cudaEventDisableTiming);
    cudaEventCreateWithFlags(&evJ, cudaEventDisableTiming);

    // ---- fork: CSR chain on s2 ----
    cudaEventRecord(evF, 0);
    cudaStreamWaitEvent(s2, evF, 0);
    zero_int_kernel<<<NBLK, 256, 0, s2>>>();
    deg_count_kernel<<<(E + 255) / 256, 256, 0, s2>>>(ei, E);
    dinv_kernel<<<NBLK, 256, 0, s2>>>();
    scan1_kernel<<<NBLK, 256, 0, s2>>>();
    scan2_kernel<<<1, 256, 0, s2>>>();
    scan3_kernel<<<NBLK, 256, 0, s2>>>();
    fill_csr_kernel<<<(E + 255) / 256, 256, 0, s2>>>(ei, E);
    cudaEventRecord(evJ, s2);

    // ---- main stream: pack + GEMMs ----
    {
        dim3 pg((256 * 256 + 255) / 256, 5);
        pack_weights_kernel<<<pg, 256>>>(W1, Wg1, Wg2, W2, W3);
    }

    // layer 1: h = relu(x @ W1 + b1)
    hmma_gemm_kernel<true, true><<<GEMM_GRID, 256, SM128>>>(
        x, ph + 0 * WPACK, b1, h, NN, DIN);

    // conv 1 GEMM
    hmma_gemm_kernel<false, false><<<GEMM_GRID, 256, SM256>>>(
        h, ph + 1 * WPACK, nullptr, hW, NN, HH);

    // join: gather needs CSR + dinv
    cudaStreamWaitEvent(0, evJ, 0);
    gather_kernel<<<NODE_WARPS, 256>>>(hW, bg1, h);

    // conv 2
    hmma_gemm_kernel<false, false><<<GEMM_GRID, 256, SM256>>>(
        h, ph + 2 * WPACK, nullptr, hW, NN, HH);
    gather_kernel<<<NODE_WARPS, 256>>>(hW, bg2, h);

    // layer 4: hW = relu(h @ W2 + b2)
    hmma_gemm_kernel<true, true><<<GEMM_GRID, 256, SM256>>>(
        h, ph + 3 * WPACK, b2, hW, NN, HH);

    // layer 5 logits: agg = hW @ W3 + b3
    hmma_gemm_kernel<true, false><<<GEMM_GRID, 256, SM256>>>(
        hW, ph + 4 * WPACK, b3, agg, NN, HH);

    // softmax -> out
    softmax_kernel<<<(NN * 32 + 255) / 256, 256>>>(agg, out);
}